// round 9
// baseline (speedup 1.0000x reference)
#include <cuda_runtime.h>
#include <math.h>

// Problem constants (fixed by the dataset)
#define NMAX   50000
#define EMAX   800000
#define IN_C   128
#define HID_C  128
#define OUT_C  64

// ---------------- device scratch (no allocations allowed) ----------------
__device__ int   g_is64;                  // 1 if edge_index is int64, 0 if int32
__device__ float g_deg [NMAX];
__device__ float g_dinv[NMAX];
__device__ int   g_cnt [NMAX];
__device__ int   g_rowptr[NMAX + 1];
__device__ int   g_cur [NMAX];
__device__ int2  g_cv  [EMAX];            // packed (col, val bits) sorted by row
__device__ float g_xw  [NMAX * HID_C];    // x @ w1
__device__ float g_h   [NMAX * HID_C];    // relu(spmm(xw)+b1)
__device__ float g_hw  [NMAX * OUT_C];    // h @ w2
__device__ float g_lab [2][NMAX * OUT_C]; // LPA ping-pong

__device__ __forceinline__ int load_idx(const void* p, size_t i, int is64) {
    if (is64) return (int)((const long long*)p)[i];
    return ((const int*)p)[i];
}

// ---------------- preprocessing kernels ----------------
// zero + edge-index dtype detection fused
__global__ void k_zero(const void* __restrict__ ei, int E, int n) {
    int i = blockIdx.x * blockDim.x + threadIdx.x;
    if (i < n) { g_deg[i] = 0.f; g_cnt[i] = 0; }
    if (i == 0) {
        const long long* q = (const long long*)ei;
        int ok64 = 1;
        int lim = (2 * E < 64) ? 2 * E : 64;   // first 512B: safe for either dtype
        for (int j = 0; j < lim; j++) {
            long long v = q[j];
            if (v < 0 || v >= (long long)n) { ok64 = 0; break; }
        }
        g_is64 = ok64;
    }
}

__global__ void k_deg(const void* __restrict__ ei,
                      const float* __restrict__ ea, int E, int N) {
    int e = blockIdx.x * blockDim.x + threadIdx.x;
    if (e < E) {
        int is64 = g_is64;
        int r = load_idx(ei, e, is64);
        if ((unsigned)r < (unsigned)N) {
            atomicAdd(&g_deg[r], ea[e]);
            atomicAdd(&g_cnt[r], 1);
        }
    }
}

// dinv + one-block exclusive scan of g_cnt -> g_rowptr / g_cur (fused)
__global__ void k_scan(int n) {
    __shared__ int sums[1024];
    int tid = threadIdx.x;
    for (int i = tid; i < n; i += 1024) {
        float d = g_deg[i];
        g_dinv[i] = (d != 0.f) ? (1.f / d) : 0.f;
    }
    int chunk = (n + 1023) / 1024;
    int start = tid * chunk;
    int end   = min(start + chunk, n);
    int s = 0;
    for (int i = start; i < end; i++) s += g_cnt[i];
    sums[tid] = s;
    __syncthreads();
    for (int off = 1; off < 1024; off <<= 1) {
        int v = (tid >= off) ? sums[tid - off] : 0;
        __syncthreads();
        sums[tid] += v;
        __syncthreads();
    }
    int run = sums[tid] - s;      // exclusive prefix
    for (int i = start; i < end; i++) {
        g_rowptr[i] = run;
        g_cur[i]    = run;
        run += g_cnt[i];
    }
    if (tid == 1023) g_rowptr[n] = sums[1023];
}

__global__ void k_scatter(const void* __restrict__ ei,
                          const float* __restrict__ ea, int E, int N) {
    int e = blockIdx.x * blockDim.x + threadIdx.x;
    if (e < E) {
        int is64 = g_is64;
        int r = load_idx(ei, e, is64);
        int c = load_idx(ei, (size_t)E + e, is64);
        if ((unsigned)r < (unsigned)N && (unsigned)c < (unsigned)N) {
            int pos = atomicAdd(&g_cur[r], 1);
            float v = ea[e] * g_dinv[r];
            g_cv[pos] = make_int2(c, __float_as_int(v));
        }
    }
}

// ---------------- dense GEMM: out[n,Ctot] = A[n,128] @ W[128,Ctot] --------
// 128x64 tile, 128 threads, 8x8 register blocking.
// As[k][row] with ld=132 (multiple of 4 -> all float4 accesses 16B-aligned),
// Bs[k][c] with ld=68. smem = 100 KB -> 2 CTAs/SM.
#define AS_LD 132
#define BS_LD 68
#define GEMM_SMEM ((128 * AS_LD + 128 * BS_LD) * (int)sizeof(float))

__global__ __launch_bounds__(128) void k_gemm(const float* __restrict__ A,
                                              const float* __restrict__ W,
                                              float* __restrict__ out,
                                              int n, int Ctot) {
    extern __shared__ float sm[];
    float* As = sm;                    // [128][AS_LD], As[k*AS_LD + row]
    float* Bs = sm + 128 * AS_LD;      // [128][BS_LD], Bs[k*BS_LD + c]
    int rowbase = blockIdx.x * 128;
    int colbase = blockIdx.y * 64;
    int tid = threadIdx.x;

    // load W tile: Bs[k][c], 128x64 floats (2048 float4 / 128 thr = 16 each)
#pragma unroll
    for (int i = tid; i < 128 * 16; i += 128) {
        int k = i >> 4, c4 = i & 15;
        *(float4*)&Bs[k * BS_LD + c4 * 4] =
            *(const float4*)&W[(size_t)k * Ctot + colbase + c4 * 4];
    }
    // load A tile transposed: As[k][row], 128x128 floats (4096 float4 / 128 thr = 32 each)
#pragma unroll
    for (int i = tid; i < 128 * 32; i += 128) {
        int row = i >> 5, k4 = i & 31;
        int grow = rowbase + row;
        if (grow >= n) grow = n - 1;   // clamp; OOB rows never stored
        float4 v = *(const float4*)&A[(size_t)grow * 128 + k4 * 4];
        As[(k4 * 4 + 0) * AS_LD + row] = v.x;
        As[(k4 * 4 + 1) * AS_LD + row] = v.y;
        As[(k4 * 4 + 2) * AS_LD + row] = v.z;
        As[(k4 * 4 + 3) * AS_LD + row] = v.w;
    }
    __syncthreads();

    int tc = tid & 7;        // col group: 8 cols each
    int tr = tid >> 3;       // row group: 8 rows each (16 groups)
    float acc[8][8] = {};
#pragma unroll 4
    for (int k = 0; k < 128; k++) {
        float a[8], b[8];
        *(float4*)&a[0] = *(float4*)&As[k * AS_LD + tr * 8];
        *(float4*)&a[4] = *(float4*)&As[k * AS_LD + tr * 8 + 4];
        *(float4*)&b[0] = *(float4*)&Bs[k * BS_LD + tc * 8];
        *(float4*)&b[4] = *(float4*)&Bs[k * BS_LD + tc * 8 + 4];
#pragma unroll
        for (int i = 0; i < 8; i++)
#pragma unroll
            for (int j = 0; j < 8; j++)
                acc[i][j] += a[i] * b[j];
    }

#pragma unroll
    for (int i = 0; i < 8; i++) {
        int row = rowbase + tr * 8 + i;
        if (row < n) {
            float4 o0 = {acc[i][0], acc[i][1], acc[i][2], acc[i][3]};
            float4 o1 = {acc[i][4], acc[i][5], acc[i][6], acc[i][7]};
            *(float4*)&out[(size_t)row * Ctot + colbase + tc * 8]     = o0;
            *(float4*)&out[(size_t)row * Ctot + colbase + tc * 8 + 4] = o1;
        }
    }
}

// ---------------- SPMM: dst[r,:] = sum_{j in row r} val_j * src[col_j,:] --
// 4-way edge unroll for gather MLP.
// EPI: 0 = none, 1 = relu(+bias), 2 = sigmoid(+bias), 3 = sigmoid (no bias)
template <int F, int EPI>
__global__ __launch_bounds__(256) void k_spmm(const float* __restrict__ src,
                                              const float* __restrict__ bias,
                                              float* __restrict__ dst, int n) {
    int w = (blockIdx.x * blockDim.x + threadIdx.x) >> 5;
    int lane = threadIdx.x & 31;
    if (w >= n) return;
    int beg = g_rowptr[w];
    int end = g_rowptr[w + 1];

    if (F == 128) {
        float4 acc = {0.f, 0.f, 0.f, 0.f};
        int j = beg;
        for (; j + 3 < end; j += 4) {
            int2 cv0 = g_cv[j];
            int2 cv1 = g_cv[j + 1];
            int2 cv2 = g_cv[j + 2];
            int2 cv3 = g_cv[j + 3];
            float4 s0 = *(const float4*)&src[(size_t)cv0.x * 128 + lane * 4];
            float4 s1 = *(const float4*)&src[(size_t)cv1.x * 128 + lane * 4];
            float4 s2 = *(const float4*)&src[(size_t)cv2.x * 128 + lane * 4];
            float4 s3 = *(const float4*)&src[(size_t)cv3.x * 128 + lane * 4];
            float v0 = __int_as_float(cv0.y);
            float v1 = __int_as_float(cv1.y);
            float v2 = __int_as_float(cv2.y);
            float v3 = __int_as_float(cv3.y);
            acc.x += v0 * s0.x; acc.y += v0 * s0.y; acc.z += v0 * s0.z; acc.w += v0 * s0.w;
            acc.x += v1 * s1.x; acc.y += v1 * s1.y; acc.z += v1 * s1.z; acc.w += v1 * s1.w;
            acc.x += v2 * s2.x; acc.y += v2 * s2.y; acc.z += v2 * s2.z; acc.w += v2 * s2.w;
            acc.x += v3 * s3.x; acc.y += v3 * s3.y; acc.z += v3 * s3.z; acc.w += v3 * s3.w;
        }
        for (; j < end; j++) {
            int2 cv = g_cv[j];
            float v = __int_as_float(cv.y);
            float4 s = *(const float4*)&src[(size_t)cv.x * 128 + lane * 4];
            acc.x += v * s.x; acc.y += v * s.y; acc.z += v * s.z; acc.w += v * s.w;
        }
        if (EPI == 1) {
            float4 b = *(const float4*)&bias[lane * 4];
            acc.x = fmaxf(acc.x + b.x, 0.f);
            acc.y = fmaxf(acc.y + b.y, 0.f);
            acc.z = fmaxf(acc.z + b.z, 0.f);
            acc.w = fmaxf(acc.w + b.w, 0.f);
        }
        *(float4*)&dst[(size_t)w * 128 + lane * 4] = acc;
    } else {  // F == 64
        float2 acc = {0.f, 0.f};
        int j = beg;
        for (; j + 3 < end; j += 4) {
            int2 cv0 = g_cv[j];
            int2 cv1 = g_cv[j + 1];
            int2 cv2 = g_cv[j + 2];
            int2 cv3 = g_cv[j + 3];
            float2 s0 = *(const float2*)&src[(size_t)cv0.x * 64 + lane * 2];
            float2 s1 = *(const float2*)&src[(size_t)cv1.x * 64 + lane * 2];
            float2 s2 = *(const float2*)&src[(size_t)cv2.x * 64 + lane * 2];
            float2 s3 = *(const float2*)&src[(size_t)cv3.x * 64 + lane * 2];
            float v0 = __int_as_float(cv0.y);
            float v1 = __int_as_float(cv1.y);
            float v2 = __int_as_float(cv2.y);
            float v3 = __int_as_float(cv3.y);
            acc.x += v0 * s0.x; acc.y += v0 * s0.y;
            acc.x += v1 * s1.x; acc.y += v1 * s1.y;
            acc.x += v2 * s2.x; acc.y += v2 * s2.y;
            acc.x += v3 * s3.x; acc.y += v3 * s3.y;
        }
        for (; j < end; j++) {
            int2 cv = g_cv[j];
            float v = __int_as_float(cv.y);
            float2 s = *(const float2*)&src[(size_t)cv.x * 64 + lane * 2];
            acc.x += v * s.x; acc.y += v * s.y;
        }
        if (EPI == 2) {
            float2 b = *(const float2*)&bias[lane * 2];
            acc.x = 1.f / (1.f + __expf(-(acc.x + b.x)));
            acc.y = 1.f / (1.f + __expf(-(acc.y + b.y)));
        } else if (EPI == 3) {
            acc.x = 1.f / (1.f + __expf(-acc.x));
            acc.y = 1.f / (1.f + __expf(-acc.y));
        }
        *(float2*)&dst[(size_t)w * 64 + lane * 2] = acc;
    }
}

// ---------------- host launch ----------------
static void* sym_addr(const void* sym) {
    void* p = nullptr;
    cudaGetSymbolAddress(&p, sym);
    return p;
}

extern "C" void kernel_launch(void* const* d_in, const int* in_sizes, int n_in,
                              void* d_out, int out_size) {
    const float* x    = (const float*)d_in[0];
    const float* soft = (const float*)d_in[1];
    const float* ea   = (const float*)d_in[2];
    const float* w1   = (const float*)d_in[3];
    const float* b1   = (const float*)d_in[4];
    const float* w2   = (const float*)d_in[5];
    const float* b2   = (const float*)d_in[6];
    const void*  ei   = (const void*)d_in[7];   // int32 or int64, device-detected

    int N = in_sizes[0] / IN_C;
    int E = in_sizes[2];

    float* out     = (float*)d_out;
    float* out_x   = out;
    float* out_lab = out + (size_t)N * OUT_C;

    float* xw = (float*)sym_addr(g_xw);
    float* h  = (float*)sym_addr(g_h);
    float* hw = (float*)sym_addr(g_hw);
    float* la = (float*)sym_addr(g_lab);
    float* lb = la + (size_t)NMAX * OUT_C;

    cudaFuncSetAttribute(k_gemm, cudaFuncAttributeMaxDynamicSharedMemorySize, GEMM_SMEM);

    int tb = 256;
    int spmm_blocks = (N + 7) / 8;  // warp per row, 8 warps/block

    // launch order keeps GEMM1 at index 3 (the launch ncu -s profiles)
    k_zero   <<<(N + tb - 1) / tb, tb>>>(ei, E, N);                 // 0
    k_deg    <<<(E + tb - 1) / tb, tb>>>(ei, ea, E, N);             // 1
    k_scan   <<<1, 1024>>>(N);                                      // 2

    dim3 g1((N + 127) / 128, 2);
    k_gemm<<<g1, 128, GEMM_SMEM>>>(x, w1, xw, N, HID_C);            // 3 <- profiled

    k_scatter<<<(E + tb - 1) / tb, tb>>>(ei, ea, E, N);             // 4

    k_spmm<128, 1><<<spmm_blocks, 256>>>(xw, b1, h, N);             // 5

    k_spmm<64, 0><<<spmm_blocks, 256>>>(soft, nullptr, la, N);      // 6 (LPA 1)

    dim3 g2((N + 127) / 128, 1);
    k_gemm<<<g2, 128, GEMM_SMEM>>>(h, w2, hw, N, OUT_C);            // 7

    k_spmm<64, 0><<<spmm_blocks, 256>>>(la, nullptr, lb, N);        // 8 (LPA 2)
    k_spmm<64, 2><<<spmm_blocks, 256>>>(hw, b2, out_x, N);          // 9
    k_spmm<64, 0><<<spmm_blocks, 256>>>(lb, nullptr, la, N);        // 10 (LPA 3)
    k_spmm<64, 0><<<spmm_blocks, 256>>>(la, nullptr, lb, N);        // 11 (LPA 4)
    k_spmm<64, 3><<<spmm_blocks, 256>>>(lb, nullptr, out_lab, N);   // 12 (LPA 5)
}

// round 10
// speedup vs baseline: 1.0601x; 1.0601x over previous
#include <cuda_runtime.h>
#include <cuda_fp16.h>
#include <math.h>

// Problem constants (fixed by the dataset)
#define NMAX   50000
#define EMAX   800000
#define IN_C   128
#define HID_C  128
#define OUT_C  64

// ---------------- device scratch (no allocations allowed) ----------------
__device__ int    g_is64;                    // 1 if edge_index is int64, 0 if int32
__device__ float  g_deg [NMAX];
__device__ float  g_dinv[NMAX];
__device__ int    g_cnt [NMAX];
__device__ int    g_rowptr[NMAX + 1];
__device__ int    g_cur [NMAX];
__device__ int2   g_cv  [EMAX];              // packed (col, val bits) sorted by row
__device__ __half g_xw  [NMAX * HID_C];      // x @ w1           (fp16 storage)
__device__ float  g_h   [NMAX * HID_C];      // relu(spmm(xw)+b1) (fp32, feeds GEMM2)
__device__ __half g_hw  [NMAX * OUT_C];      // h @ w2           (fp16 storage)
__device__ __half g_lab [2][NMAX * OUT_C];   // LPA ping-pong    (fp16 storage)

__device__ __forceinline__ int load_idx(const void* p, size_t i, int is64) {
    if (is64) return (int)((const long long*)p)[i];
    return ((const int*)p)[i];
}

// ---------------- gather/store helpers (fp32 / fp16 overloads) -----------
__device__ __forceinline__ float4 gather4(const float* src, int col, int lane) {
    return *(const float4*)&src[(size_t)col * 128 + lane * 4];
}
__device__ __forceinline__ float4 gather4(const __half* src, int col, int lane) {
    uint2 raw = *(const uint2*)&src[(size_t)col * 128 + lane * 4];
    float2 lo = __half22float2(*(__half2*)&raw.x);
    float2 hi = __half22float2(*(__half2*)&raw.y);
    return make_float4(lo.x, lo.y, hi.x, hi.y);
}
__device__ __forceinline__ float2 gather2(const float* src, int col, int lane) {
    return *(const float2*)&src[(size_t)col * 64 + lane * 2];
}
__device__ __forceinline__ float2 gather2(const __half* src, int col, int lane) {
    return __half22float2(*(const __half2*)&src[(size_t)col * 64 + lane * 2]);
}
__device__ __forceinline__ void store4e(float* dst, size_t idx, float4 v) {
    *(float4*)&dst[idx] = v;
}
__device__ __forceinline__ void store4e(__half* dst, size_t idx, float4 v) {
    __half2 h0 = __floats2half2_rn(v.x, v.y);
    __half2 h1 = __floats2half2_rn(v.z, v.w);
    uint2 raw = {*(unsigned*)&h0, *(unsigned*)&h1};
    *(uint2*)&dst[idx] = raw;
}
__device__ __forceinline__ void store2e(float* dst, size_t idx, float2 v) {
    *(float2*)&dst[idx] = v;
}
__device__ __forceinline__ void store2e(__half* dst, size_t idx, float2 v) {
    *(__half2*)&dst[idx] = __floats2half2_rn(v.x, v.y);
}

// ---------------- preprocessing kernels ----------------
// zero + edge-index dtype detection fused
__global__ void k_zero(const void* __restrict__ ei, int E, int n) {
    int i = blockIdx.x * blockDim.x + threadIdx.x;
    if (i < n) { g_deg[i] = 0.f; g_cnt[i] = 0; }
    if (i == 0) {
        const long long* q = (const long long*)ei;
        int ok64 = 1;
        int lim = (2 * E < 64) ? 2 * E : 64;   // first 512B: safe for either dtype
        for (int j = 0; j < lim; j++) {
            long long v = q[j];
            if (v < 0 || v >= (long long)n) { ok64 = 0; break; }
        }
        g_is64 = ok64;
    }
}

__global__ void k_deg(const void* __restrict__ ei,
                      const float* __restrict__ ea, int E, int N) {
    int e = blockIdx.x * blockDim.x + threadIdx.x;
    if (e < E) {
        int is64 = g_is64;
        int r = load_idx(ei, e, is64);
        if ((unsigned)r < (unsigned)N) {
            atomicAdd(&g_deg[r], ea[e]);
            atomicAdd(&g_cnt[r], 1);
        }
    }
}

// dinv + one-block exclusive scan of g_cnt -> g_rowptr / g_cur (fused)
__global__ void k_scan(int n) {
    __shared__ int sums[1024];
    int tid = threadIdx.x;
    for (int i = tid; i < n; i += 1024) {
        float d = g_deg[i];
        g_dinv[i] = (d != 0.f) ? (1.f / d) : 0.f;
    }
    int chunk = (n + 1023) / 1024;
    int start = tid * chunk;
    int end   = min(start + chunk, n);
    int s = 0;
    for (int i = start; i < end; i++) s += g_cnt[i];
    sums[tid] = s;
    __syncthreads();
    for (int off = 1; off < 1024; off <<= 1) {
        int v = (tid >= off) ? sums[tid - off] : 0;
        __syncthreads();
        sums[tid] += v;
        __syncthreads();
    }
    int run = sums[tid] - s;      // exclusive prefix
    for (int i = start; i < end; i++) {
        g_rowptr[i] = run;
        g_cur[i]    = run;
        run += g_cnt[i];
    }
    if (tid == 1023) g_rowptr[n] = sums[1023];
}

__global__ void k_scatter(const void* __restrict__ ei,
                          const float* __restrict__ ea, int E, int N) {
    int e = blockIdx.x * blockDim.x + threadIdx.x;
    if (e < E) {
        int is64 = g_is64;
        int r = load_idx(ei, e, is64);
        int c = load_idx(ei, (size_t)E + e, is64);
        if ((unsigned)r < (unsigned)N && (unsigned)c < (unsigned)N) {
            int pos = atomicAdd(&g_cur[r], 1);
            float v = ea[e] * g_dinv[r];
            g_cv[pos] = make_int2(c, __float_as_int(v));
        }
    }
}

// ---------------- dense GEMM: out[n,Ctot] = A[n,128] @ W[128,Ctot] --------
// 128x64 tile, 128 threads, 8x8 register blocking, OutT epilogue (fp32/fp16).
#define AS_LD 132
#define BS_LD 68
#define GEMM_SMEM ((128 * AS_LD + 128 * BS_LD) * (int)sizeof(float))

template <typename OutT>
__global__ __launch_bounds__(128) void k_gemm(const float* __restrict__ A,
                                              const float* __restrict__ W,
                                              OutT* __restrict__ out,
                                              int n, int Ctot) {
    extern __shared__ float sm[];
    float* As = sm;                    // [128][AS_LD], As[k*AS_LD + row]
    float* Bs = sm + 128 * AS_LD;      // [128][BS_LD], Bs[k*BS_LD + c]
    int rowbase = blockIdx.x * 128;
    int colbase = blockIdx.y * 64;
    int tid = threadIdx.x;

#pragma unroll
    for (int i = tid; i < 128 * 16; i += 128) {
        int k = i >> 4, c4 = i & 15;
        *(float4*)&Bs[k * BS_LD + c4 * 4] =
            *(const float4*)&W[(size_t)k * Ctot + colbase + c4 * 4];
    }
#pragma unroll
    for (int i = tid; i < 128 * 32; i += 128) {
        int row = i >> 5, k4 = i & 31;
        int grow = rowbase + row;
        if (grow >= n) grow = n - 1;   // clamp; OOB rows never stored
        float4 v = *(const float4*)&A[(size_t)grow * 128 + k4 * 4];
        As[(k4 * 4 + 0) * AS_LD + row] = v.x;
        As[(k4 * 4 + 1) * AS_LD + row] = v.y;
        As[(k4 * 4 + 2) * AS_LD + row] = v.z;
        As[(k4 * 4 + 3) * AS_LD + row] = v.w;
    }
    __syncthreads();

    int tc = tid & 7;        // col group: 8 cols each
    int tr = tid >> 3;       // row group: 8 rows each (16 groups)
    float acc[8][8] = {};
#pragma unroll 4
    for (int k = 0; k < 128; k++) {
        float a[8], b[8];
        *(float4*)&a[0] = *(float4*)&As[k * AS_LD + tr * 8];
        *(float4*)&a[4] = *(float4*)&As[k * AS_LD + tr * 8 + 4];
        *(float4*)&b[0] = *(float4*)&Bs[k * BS_LD + tc * 8];
        *(float4*)&b[4] = *(float4*)&Bs[k * BS_LD + tc * 8 + 4];
#pragma unroll
        for (int i = 0; i < 8; i++)
#pragma unroll
            for (int j = 0; j < 8; j++)
                acc[i][j] += a[i] * b[j];
    }

#pragma unroll
    for (int i = 0; i < 8; i++) {
        int row = rowbase + tr * 8 + i;
        if (row < n) {
            size_t base = (size_t)row * Ctot + colbase + tc * 8;
            store4e(out, base,     make_float4(acc[i][0], acc[i][1], acc[i][2], acc[i][3]));
            store4e(out, base + 4, make_float4(acc[i][4], acc[i][5], acc[i][6], acc[i][7]));
        }
    }
}

// ---------------- SPMM: dst[r,:] = sum_{j in row r} val_j * src[col_j,:] --
// 4-way edge unroll. SrcT/DstT in {float, __half}; accumulation in fp32.
// EPI: 0 = none, 1 = relu(+bias), 2 = sigmoid(+bias), 3 = sigmoid (no bias)
template <int F, int EPI, typename SrcT, typename DstT>
__global__ __launch_bounds__(256) void k_spmm(const SrcT* __restrict__ src,
                                              const float* __restrict__ bias,
                                              DstT* __restrict__ dst, int n) {
    int w = (blockIdx.x * blockDim.x + threadIdx.x) >> 5;
    int lane = threadIdx.x & 31;
    if (w >= n) return;
    int beg = g_rowptr[w];
    int end = g_rowptr[w + 1];

    if (F == 128) {
        float4 acc = {0.f, 0.f, 0.f, 0.f};
        int j = beg;
        for (; j + 3 < end; j += 4) {
            int2 cv0 = g_cv[j];
            int2 cv1 = g_cv[j + 1];
            int2 cv2 = g_cv[j + 2];
            int2 cv3 = g_cv[j + 3];
            float4 s0 = gather4(src, cv0.x, lane);
            float4 s1 = gather4(src, cv1.x, lane);
            float4 s2 = gather4(src, cv2.x, lane);
            float4 s3 = gather4(src, cv3.x, lane);
            float v0 = __int_as_float(cv0.y);
            float v1 = __int_as_float(cv1.y);
            float v2 = __int_as_float(cv2.y);
            float v3 = __int_as_float(cv3.y);
            acc.x += v0 * s0.x; acc.y += v0 * s0.y; acc.z += v0 * s0.z; acc.w += v0 * s0.w;
            acc.x += v1 * s1.x; acc.y += v1 * s1.y; acc.z += v1 * s1.z; acc.w += v1 * s1.w;
            acc.x += v2 * s2.x; acc.y += v2 * s2.y; acc.z += v2 * s2.z; acc.w += v2 * s2.w;
            acc.x += v3 * s3.x; acc.y += v3 * s3.y; acc.z += v3 * s3.z; acc.w += v3 * s3.w;
        }
        for (; j < end; j++) {
            int2 cv = g_cv[j];
            float v = __int_as_float(cv.y);
            float4 s = gather4(src, cv.x, lane);
            acc.x += v * s.x; acc.y += v * s.y; acc.z += v * s.z; acc.w += v * s.w;
        }
        if (EPI == 1) {
            float4 b = *(const float4*)&bias[lane * 4];
            acc.x = fmaxf(acc.x + b.x, 0.f);
            acc.y = fmaxf(acc.y + b.y, 0.f);
            acc.z = fmaxf(acc.z + b.z, 0.f);
            acc.w = fmaxf(acc.w + b.w, 0.f);
        }
        store4e(dst, (size_t)w * 128 + lane * 4, acc);
    } else {  // F == 64
        float2 acc = {0.f, 0.f};
        int j = beg;
        for (; j + 3 < end; j += 4) {
            int2 cv0 = g_cv[j];
            int2 cv1 = g_cv[j + 1];
            int2 cv2 = g_cv[j + 2];
            int2 cv3 = g_cv[j + 3];
            float2 s0 = gather2(src, cv0.x, lane);
            float2 s1 = gather2(src, cv1.x, lane);
            float2 s2 = gather2(src, cv2.x, lane);
            float2 s3 = gather2(src, cv3.x, lane);
            float v0 = __int_as_float(cv0.y);
            float v1 = __int_as_float(cv1.y);
            float v2 = __int_as_float(cv2.y);
            float v3 = __int_as_float(cv3.y);
            acc.x += v0 * s0.x; acc.y += v0 * s0.y;
            acc.x += v1 * s1.x; acc.y += v1 * s1.y;
            acc.x += v2 * s2.x; acc.y += v2 * s2.y;
            acc.x += v3 * s3.x; acc.y += v3 * s3.y;
        }
        for (; j < end; j++) {
            int2 cv = g_cv[j];
            float v = __int_as_float(cv.y);
            float2 s = gather2(src, cv.x, lane);
            acc.x += v * s.x; acc.y += v * s.y;
        }
        if (EPI == 2) {
            float2 b = *(const float2*)&bias[lane * 2];
            acc.x = 1.f / (1.f + __expf(-(acc.x + b.x)));
            acc.y = 1.f / (1.f + __expf(-(acc.y + b.y)));
        } else if (EPI == 3) {
            acc.x = 1.f / (1.f + __expf(-acc.x));
            acc.y = 1.f / (1.f + __expf(-acc.y));
        }
        store2e(dst, (size_t)w * 64 + lane * 2, acc);
    }
}

// ---------------- host launch ----------------
static void* sym_addr(const void* sym) {
    void* p = nullptr;
    cudaGetSymbolAddress(&p, sym);
    return p;
}

extern "C" void kernel_launch(void* const* d_in, const int* in_sizes, int n_in,
                              void* d_out, int out_size) {
    const float* x    = (const float*)d_in[0];
    const float* soft = (const float*)d_in[1];
    const float* ea   = (const float*)d_in[2];
    const float* w1   = (const float*)d_in[3];
    const float* b1   = (const float*)d_in[4];
    const float* w2   = (const float*)d_in[5];
    const float* b2   = (const float*)d_in[6];
    const void*  ei   = (const void*)d_in[7];   // int32 or int64, device-detected

    int N = in_sizes[0] / IN_C;
    int E = in_sizes[2];

    float* out     = (float*)d_out;
    float* out_x   = out;
    float* out_lab = out + (size_t)N * OUT_C;

    __half* xw = (__half*)sym_addr(g_xw);
    float*  h  = (float*)sym_addr(g_h);
    __half* hw = (__half*)sym_addr(g_hw);
    __half* la = (__half*)sym_addr(g_lab);
    __half* lb = la + (size_t)NMAX * OUT_C;

    cudaFuncSetAttribute(k_gemm<__half>, cudaFuncAttributeMaxDynamicSharedMemorySize, GEMM_SMEM);

    int tb = 256;
    int spmm_blocks = (N + 7) / 8;  // warp per row, 8 warps/block

    // launch order keeps GEMM1 at index 3 (the launch ncu -s profiles)
    k_zero   <<<(N + tb - 1) / tb, tb>>>(ei, E, N);                 // 0
    k_deg    <<<(E + tb - 1) / tb, tb>>>(ei, ea, E, N);             // 1
    k_scan   <<<1, 1024>>>(N);                                      // 2

    dim3 g1((N + 127) / 128, 2);
    k_gemm<__half><<<g1, 128, GEMM_SMEM>>>(x, w1, xw, N, HID_C);    // 3 <- profiled

    k_scatter<<<(E + tb - 1) / tb, tb>>>(ei, ea, E, N);             // 4

    k_spmm<128, 1, __half, float><<<spmm_blocks, 256>>>(xw, b1, h, N);          // 5

    k_spmm<64, 0, float, __half><<<spmm_blocks, 256>>>(soft, nullptr, la, N);   // 6 (LPA 1)

    dim3 g2((N + 127) / 128, 1);
    k_gemm<__half><<<g2, 128, GEMM_SMEM>>>(h, w2, hw, N, OUT_C);    // 7

    k_spmm<64, 0, __half, __half><<<spmm_blocks, 256>>>(la, nullptr, lb, N);    // 8 (LPA 2)
    k_spmm<64, 2, __half, float ><<<spmm_blocks, 256>>>(hw, b2, out_x, N);      // 9
    k_spmm<64, 0, __half, __half><<<spmm_blocks, 256>>>(lb, nullptr, la, N);    // 10 (LPA 3)
    k_spmm<64, 0, __half, __half><<<spmm_blocks, 256>>>(la, nullptr, lb, N);    // 11 (LPA 4)
    k_spmm<64, 3, __half, float ><<<spmm_blocks, 256>>>(lb, nullptr, out_lab, N); // 12 (LPA 5)
}

// round 11
// speedup vs baseline: 1.3632x; 1.2858x over previous
#include <cuda_runtime.h>
#include <cuda_fp16.h>
#include <math.h>

// Problem constants (fixed by the dataset)
#define NMAX   50000
#define EMAX   800000
#define IN_C   128
#define HID_C  128
#define OUT_C  64

// ---------------- device scratch (no allocations allowed) ----------------
__device__ int    g_is64;                    // 1 if edge_index is int64, 0 if int32
__device__ float  g_deg [NMAX];
__device__ int    g_cnt [NMAX];
__device__ int    g_bsum[256];               // per-block partial sums (196 used)
__device__ int    g_rowptr[NMAX + 1];
__device__ int    g_cur [NMAX];
__device__ int2   g_cv  [EMAX];              // packed (col, val bits) sorted by row
__device__ __half g_xw  [NMAX * HID_C];      // x @ w1            (fp16 storage)
__device__ float  g_h   [NMAX * HID_C];      // relu(spmm(xw)+b1) (fp32, feeds GEMM2)
__device__ __half g_hw  [NMAX * OUT_C];      // h @ w2            (fp16 storage)
__device__ __half g_lab [2][NMAX * OUT_C];   // LPA ping-pong     (fp16 storage)

__device__ __forceinline__ int load_idx(const void* p, size_t i, int is64) {
    if (is64) return (int)((const long long*)p)[i];
    return ((const int*)p)[i];
}

// ---------------- gather/store helpers (fp32 / fp16 overloads) -----------
__device__ __forceinline__ float4 gather4(const float* src, int col, int lane) {
    return *(const float4*)&src[(size_t)col * 128 + lane * 4];
}
__device__ __forceinline__ float4 gather4(const __half* src, int col, int lane) {
    uint2 raw = *(const uint2*)&src[(size_t)col * 128 + lane * 4];
    float2 lo = __half22float2(*(__half2*)&raw.x);
    float2 hi = __half22float2(*(__half2*)&raw.y);
    return make_float4(lo.x, lo.y, hi.x, hi.y);
}
__device__ __forceinline__ float2 gather2(const float* src, int col, int lane) {
    return *(const float2*)&src[(size_t)col * 64 + lane * 2];
}
__device__ __forceinline__ float2 gather2(const __half* src, int col, int lane) {
    return __half22float2(*(const __half2*)&src[(size_t)col * 64 + lane * 2]);
}
__device__ __forceinline__ void store4e(float* dst, size_t idx, float4 v) {
    *(float4*)&dst[idx] = v;
}
__device__ __forceinline__ void store4e(__half* dst, size_t idx, float4 v) {
    __half2 h0 = __floats2half2_rn(v.x, v.y);
    __half2 h1 = __floats2half2_rn(v.z, v.w);
    uint2 raw = {*(unsigned*)&h0, *(unsigned*)&h1};
    *(uint2*)&dst[idx] = raw;
}
__device__ __forceinline__ void store2e(float* dst, size_t idx, float2 v) {
    *(float2*)&dst[idx] = v;
}
__device__ __forceinline__ void store2e(__half* dst, size_t idx, float2 v) {
    *(__half2*)&dst[idx] = __floats2half2_rn(v.x, v.y);
}

// ---------------- preprocessing kernels ----------------
// zero + edge-index dtype detection fused
__global__ void k_zero(const void* __restrict__ ei, int E, int n) {
    int i = blockIdx.x * blockDim.x + threadIdx.x;
    if (i < n) { g_deg[i] = 0.f; g_cnt[i] = 0; }
    if (i == 0) {
        const long long* q = (const long long*)ei;
        int ok64 = 1;
        int lim = (2 * E < 64) ? 2 * E : 64;   // first 512B: safe for either dtype
        for (int j = 0; j < lim; j++) {
            long long v = q[j];
            if (v < 0 || v >= (long long)n) { ok64 = 0; break; }
        }
        g_is64 = ok64;
    }
}

__global__ void k_deg(const void* __restrict__ ei,
                      const float* __restrict__ ea, int E, int N) {
    int e = blockIdx.x * blockDim.x + threadIdx.x;
    if (e < E) {
        int is64 = g_is64;
        int r = load_idx(ei, e, is64);
        if ((unsigned)r < (unsigned)N) {
            atomicAdd(&g_deg[r], ea[e]);
            atomicAdd(&g_cnt[r], 1);
        }
    }
}

// ---- parallel exclusive scan of g_cnt -> g_rowptr / g_cur (3 kernels) ----
__global__ __launch_bounds__(256) void k_bsum(int n) {
    __shared__ int sh[256];
    int tid = threadIdx.x;
    int i = blockIdx.x * 256 + tid;
    sh[tid] = (i < n) ? g_cnt[i] : 0;
    __syncthreads();
    for (int off = 128; off > 0; off >>= 1) {
        if (tid < off) sh[tid] += sh[tid + off];
        __syncthreads();
    }
    if (tid == 0) g_bsum[blockIdx.x] = sh[0];
}

__global__ __launch_bounds__(256) void k_bscan(int nb) {
    __shared__ int sh[256];
    int tid = threadIdx.x;
    int v = (tid < nb) ? g_bsum[tid] : 0;
    sh[tid] = v;
    __syncthreads();
    for (int off = 1; off < 256; off <<= 1) {
        int t = (tid >= off) ? sh[tid - off] : 0;
        __syncthreads();
        sh[tid] += t;
        __syncthreads();
    }
    if (tid < nb) g_bsum[tid] = sh[tid] - v;   // exclusive
}

__global__ __launch_bounds__(256) void k_rowptr(int n) {
    __shared__ int sh[256];
    int tid = threadIdx.x;
    int i = blockIdx.x * 256 + tid;
    int v = (i < n) ? g_cnt[i] : 0;
    sh[tid] = v;
    __syncthreads();
    for (int off = 1; off < 256; off <<= 1) {
        int t = (tid >= off) ? sh[tid - off] : 0;
        __syncthreads();
        sh[tid] += t;
        __syncthreads();
    }
    int incl = sh[tid];
    int base = g_bsum[blockIdx.x];
    if (i < n) {
        int ex = base + incl - v;
        g_rowptr[i] = ex;
        g_cur[i]    = ex;
        if (i == n - 1) g_rowptr[n] = base + incl;
    }
}

__global__ void k_scatter(const void* __restrict__ ei,
                          const float* __restrict__ ea, int E, int N) {
    int e = blockIdx.x * blockDim.x + threadIdx.x;
    if (e < E) {
        int is64 = g_is64;
        int r = load_idx(ei, e, is64);
        int c = load_idx(ei, (size_t)E + e, is64);
        if ((unsigned)r < (unsigned)N && (unsigned)c < (unsigned)N) {
            int pos = atomicAdd(&g_cur[r], 1);
            // any row present in an edge has deg >= 0.1 (edge_attr > 0)
            float v = ea[e] / g_deg[r];
            g_cv[pos] = make_int2(c, __float_as_int(v));
        }
    }
}

// ---------------- dense GEMM: out[n,Ctot] = A[n,128] @ W[128,Ctot] --------
// 128x64 tile, 128 threads, 8x8 register blocking, OutT epilogue (fp32/fp16).
#define AS_LD 132
#define BS_LD 68
#define GEMM_SMEM ((128 * AS_LD + 128 * BS_LD) * (int)sizeof(float))

template <typename OutT>
__global__ __launch_bounds__(128) void k_gemm(const float* __restrict__ A,
                                              const float* __restrict__ W,
                                              OutT* __restrict__ out,
                                              int n, int Ctot) {
    extern __shared__ float sm[];
    float* As = sm;                    // [128][AS_LD], As[k*AS_LD + row]
    float* Bs = sm + 128 * AS_LD;      // [128][BS_LD], Bs[k*BS_LD + c]
    int rowbase = blockIdx.x * 128;
    int colbase = blockIdx.y * 64;
    int tid = threadIdx.x;

#pragma unroll
    for (int i = tid; i < 128 * 16; i += 128) {
        int k = i >> 4, c4 = i & 15;
        *(float4*)&Bs[k * BS_LD + c4 * 4] =
            *(const float4*)&W[(size_t)k * Ctot + colbase + c4 * 4];
    }
#pragma unroll
    for (int i = tid; i < 128 * 32; i += 128) {
        int row = i >> 5, k4 = i & 31;
        int grow = rowbase + row;
        if (grow >= n) grow = n - 1;   // clamp; OOB rows never stored
        float4 v = *(const float4*)&A[(size_t)grow * 128 + k4 * 4];
        As[(k4 * 4 + 0) * AS_LD + row] = v.x;
        As[(k4 * 4 + 1) * AS_LD + row] = v.y;
        As[(k4 * 4 + 2) * AS_LD + row] = v.z;
        As[(k4 * 4 + 3) * AS_LD + row] = v.w;
    }
    __syncthreads();

    int tc = tid & 7;        // col group: 8 cols each
    int tr = tid >> 3;       // row group: 8 rows each (16 groups)
    float acc[8][8] = {};
#pragma unroll 4
    for (int k = 0; k < 128; k++) {
        float a[8], b[8];
        *(float4*)&a[0] = *(float4*)&As[k * AS_LD + tr * 8];
        *(float4*)&a[4] = *(float4*)&As[k * AS_LD + tr * 8 + 4];
        *(float4*)&b[0] = *(float4*)&Bs[k * BS_LD + tc * 8];
        *(float4*)&b[4] = *(float4*)&Bs[k * BS_LD + tc * 8 + 4];
#pragma unroll
        for (int i = 0; i < 8; i++)
#pragma unroll
            for (int j = 0; j < 8; j++)
                acc[i][j] += a[i] * b[j];
    }

#pragma unroll
    for (int i = 0; i < 8; i++) {
        int row = rowbase + tr * 8 + i;
        if (row < n) {
            size_t base = (size_t)row * Ctot + colbase + tc * 8;
            store4e(out, base,     make_float4(acc[i][0], acc[i][1], acc[i][2], acc[i][3]));
            store4e(out, base + 4, make_float4(acc[i][4], acc[i][5], acc[i][6], acc[i][7]));
        }
    }
}

// ---------------- SPMM: dst[r,:] = sum_{j in row r} val_j * src[col_j,:] --
// 4-way edge unroll. SrcT/DstT in {float, __half}; accumulation in fp32.
// EPI: 0 = none, 1 = relu(+bias), 2 = sigmoid(+bias), 3 = sigmoid (no bias)
template <int F, int EPI, typename SrcT, typename DstT>
__global__ __launch_bounds__(256) void k_spmm(const SrcT* __restrict__ src,
                                              const float* __restrict__ bias,
                                              DstT* __restrict__ dst, int n) {
    int w = (blockIdx.x * blockDim.x + threadIdx.x) >> 5;
    int lane = threadIdx.x & 31;
    if (w >= n) return;
    int beg = g_rowptr[w];
    int end = g_rowptr[w + 1];

    if (F == 128) {
        float4 acc = {0.f, 0.f, 0.f, 0.f};
        int j = beg;
        for (; j + 3 < end; j += 4) {
            int2 cv0 = g_cv[j];
            int2 cv1 = g_cv[j + 1];
            int2 cv2 = g_cv[j + 2];
            int2 cv3 = g_cv[j + 3];
            float4 s0 = gather4(src, cv0.x, lane);
            float4 s1 = gather4(src, cv1.x, lane);
            float4 s2 = gather4(src, cv2.x, lane);
            float4 s3 = gather4(src, cv3.x, lane);
            float v0 = __int_as_float(cv0.y);
            float v1 = __int_as_float(cv1.y);
            float v2 = __int_as_float(cv2.y);
            float v3 = __int_as_float(cv3.y);
            acc.x += v0 * s0.x; acc.y += v0 * s0.y; acc.z += v0 * s0.z; acc.w += v0 * s0.w;
            acc.x += v1 * s1.x; acc.y += v1 * s1.y; acc.z += v1 * s1.z; acc.w += v1 * s1.w;
            acc.x += v2 * s2.x; acc.y += v2 * s2.y; acc.z += v2 * s2.z; acc.w += v2 * s2.w;
            acc.x += v3 * s3.x; acc.y += v3 * s3.y; acc.z += v3 * s3.z; acc.w += v3 * s3.w;
        }
        for (; j < end; j++) {
            int2 cv = g_cv[j];
            float v = __int_as_float(cv.y);
            float4 s = gather4(src, cv.x, lane);
            acc.x += v * s.x; acc.y += v * s.y; acc.z += v * s.z; acc.w += v * s.w;
        }
        if (EPI == 1) {
            float4 b = *(const float4*)&bias[lane * 4];
            acc.x = fmaxf(acc.x + b.x, 0.f);
            acc.y = fmaxf(acc.y + b.y, 0.f);
            acc.z = fmaxf(acc.z + b.z, 0.f);
            acc.w = fmaxf(acc.w + b.w, 0.f);
        }
        store4e(dst, (size_t)w * 128 + lane * 4, acc);
    } else {  // F == 64
        float2 acc = {0.f, 0.f};
        int j = beg;
        for (; j + 3 < end; j += 4) {
            int2 cv0 = g_cv[j];
            int2 cv1 = g_cv[j + 1];
            int2 cv2 = g_cv[j + 2];
            int2 cv3 = g_cv[j + 3];
            float2 s0 = gather2(src, cv0.x, lane);
            float2 s1 = gather2(src, cv1.x, lane);
            float2 s2 = gather2(src, cv2.x, lane);
            float2 s3 = gather2(src, cv3.x, lane);
            float v0 = __int_as_float(cv0.y);
            float v1 = __int_as_float(cv1.y);
            float v2 = __int_as_float(cv2.y);
            float v3 = __int_as_float(cv3.y);
            acc.x += v0 * s0.x; acc.y += v0 * s0.y;
            acc.x += v1 * s1.x; acc.y += v1 * s1.y;
            acc.x += v2 * s2.x; acc.y += v2 * s2.y;
            acc.x += v3 * s3.x; acc.y += v3 * s3.y;
        }
        for (; j < end; j++) {
            int2 cv = g_cv[j];
            float v = __int_as_float(cv.y);
            float2 s = gather2(src, cv.x, lane);
            acc.x += v * s.x; acc.y += v * s.y;
        }
        if (EPI == 2) {
            float2 b = *(const float2*)&bias[lane * 2];
            acc.x = 1.f / (1.f + __expf(-(acc.x + b.x)));
            acc.y = 1.f / (1.f + __expf(-(acc.y + b.y)));
        } else if (EPI == 3) {
            acc.x = 1.f / (1.f + __expf(-acc.x));
            acc.y = 1.f / (1.f + __expf(-acc.y));
        }
        store2e(dst, (size_t)w * 64 + lane * 2, acc);
    }
}

// ---------------- host launch ----------------
static void* sym_addr(const void* sym) {
    void* p = nullptr;
    cudaGetSymbolAddress(&p, sym);
    return p;
}

extern "C" void kernel_launch(void* const* d_in, const int* in_sizes, int n_in,
                              void* d_out, int out_size) {
    const float* x    = (const float*)d_in[0];
    const float* soft = (const float*)d_in[1];
    const float* ea   = (const float*)d_in[2];
    const float* w1   = (const float*)d_in[3];
    const float* b1   = (const float*)d_in[4];
    const float* w2   = (const float*)d_in[5];
    const float* b2   = (const float*)d_in[6];
    const void*  ei   = (const void*)d_in[7];   // int32 or int64, device-detected

    int N = in_sizes[0] / IN_C;
    int E = in_sizes[2];

    float* out     = (float*)d_out;
    float* out_x   = out;
    float* out_lab = out + (size_t)N * OUT_C;

    __half* xw = (__half*)sym_addr(g_xw);
    float*  h  = (float*)sym_addr(g_h);
    __half* hw = (__half*)sym_addr(g_hw);
    __half* la = (__half*)sym_addr(g_lab);
    __half* lb = la + (size_t)NMAX * OUT_C;

    cudaFuncSetAttribute(k_gemm<__half>, cudaFuncAttributeMaxDynamicSharedMemorySize, GEMM_SMEM);

    int tb = 256;
    int nb = (N + 255) / 256;       // scan blocks (196 for N=50000, fits 256)
    int spmm_blocks = (N + 7) / 8;  // warp per row, 8 warps/block

    // launch order keeps GEMM1 at index 3 (the launch ncu -s profiles)
    k_zero  <<<(N + tb - 1) / tb, tb>>>(ei, E, N);                  // 0
    k_deg   <<<(E + tb - 1) / tb, tb>>>(ei, ea, E, N);              // 1
    k_bsum  <<<nb, 256>>>(N);                                       // 2

    dim3 g1((N + 127) / 128, 2);
    k_gemm<__half><<<g1, 128, GEMM_SMEM>>>(x, w1, xw, N, HID_C);    // 3 <- profiled

    k_bscan <<<1, 256>>>(nb);                                       // 4
    k_rowptr<<<nb, 256>>>(N);                                       // 5
    k_scatter<<<(E + tb - 1) / tb, tb>>>(ei, ea, E, N);             // 6

    k_spmm<128, 1, __half, float><<<spmm_blocks, 256>>>(xw, b1, h, N);          // 7

    k_spmm<64, 0, float, __half><<<spmm_blocks, 256>>>(soft, nullptr, la, N);   // 8 (LPA 1)

    dim3 g2((N + 127) / 128, 1);
    k_gemm<__half><<<g2, 128, GEMM_SMEM>>>(h, w2, hw, N, OUT_C);    // 9

    k_spmm<64, 0, __half, __half><<<spmm_blocks, 256>>>(la, nullptr, lb, N);    // 10 (LPA 2)
    k_spmm<64, 2, __half, float ><<<spmm_blocks, 256>>>(hw, b2, out_x, N);      // 11
    k_spmm<64, 0, __half, __half><<<spmm_blocks, 256>>>(lb, nullptr, la, N);    // 12 (LPA 3)
    k_spmm<64, 0, __half, __half><<<spmm_blocks, 256>>>(la, nullptr, lb, N);    // 13 (LPA 4)
    k_spmm<64, 3, __half, float ><<<spmm_blocks, 256>>>(lb, nullptr, out_lab, N); // 14 (LPA 5)
}

// round 15
// speedup vs baseline: 1.5386x; 1.1287x over previous
#include <cuda_runtime.h>
#include <cuda_fp16.h>
#include <mma.h>
#include <math.h>

using namespace nvcuda;

// Problem constants (fixed by the dataset)
#define NMAX     50000
#define NMAX_PAD 50016      // multiple of 32 (warp row-tile)
#define EMAX     800000
#define IN_C     128
#define HID_C    128
#define OUT_C    64

// ---------------- device scratch (no allocations allowed) ----------------
__device__ int    g_is64;
__device__ float  g_deg [NMAX];
__device__ int    g_cnt [NMAX];
__device__ int    g_bsum[256];
__device__ int    g_rowptr[NMAX + 1];
__device__ int    g_cur [NMAX];
__device__ int2   g_cv  [EMAX];
__device__ __half g_xh  [NMAX_PAD * IN_C];    // x in fp16 (pad rows zero)
__device__ __half g_w1h [IN_C * HID_C];
__device__ __half g_w2h [HID_C * OUT_C];
__device__ __half g_xw  [NMAX_PAD * HID_C];   // x @ w1
__device__ __half g_h   [NMAX_PAD * HID_C];   // relu(spmm(xw)+b1)  (pad rows stay 0)
__device__ __half g_hw  [NMAX_PAD * OUT_C];   // h @ w2
__device__ __half g_lab [2][NMAX * OUT_C];    // LPA ping-pong

__device__ __forceinline__ int load_idx(const void* p, size_t i, int is64) {
    if (is64) return (int)((const long long*)p)[i];
    return ((const int*)p)[i];
}

// ---------------- gather/store helpers ----------------
__device__ __forceinline__ float4 gather4(const float* src, int col, int lane) {
    return *(const float4*)&src[(size_t)col * 128 + lane * 4];
}
__device__ __forceinline__ float4 gather4(const __half* src, int col, int lane) {
    uint2 raw = *(const uint2*)&src[(size_t)col * 128 + lane * 4];
    float2 lo = __half22float2(*(__half2*)&raw.x);
    float2 hi = __half22float2(*(__half2*)&raw.y);
    return make_float4(lo.x, lo.y, hi.x, hi.y);
}
__device__ __forceinline__ float2 gather2(const float* src, int col, int lane) {
    return *(const float2*)&src[(size_t)col * 64 + lane * 2];
}
__device__ __forceinline__ float2 gather2(const __half* src, int col, int lane) {
    return __half22float2(*(const __half2*)&src[(size_t)col * 64 + lane * 2]);
}
__device__ __forceinline__ void store4e(float* dst, size_t idx, float4 v) {
    *(float4*)&dst[idx] = v;
}
__device__ __forceinline__ void store4e(__half* dst, size_t idx, float4 v) {
    __half2 h0 = __floats2half2_rn(v.x, v.y);
    __half2 h1 = __floats2half2_rn(v.z, v.w);
    uint2 raw = {*(unsigned*)&h0, *(unsigned*)&h1};
    *(uint2*)&dst[idx] = raw;
}
__device__ __forceinline__ void store2e(float* dst, size_t idx, float2 v) {
    *(float2*)&dst[idx] = v;
}
__device__ __forceinline__ void store2e(__half* dst, size_t idx, float2 v) {
    *(__half2*)&dst[idx] = __floats2half2_rn(v.x, v.y);
}

// ---------------- preprocessing kernels ----------------
__global__ void k_zero(const void* __restrict__ ei, int E, int n) {
    int i = blockIdx.x * blockDim.x + threadIdx.x;
    if (i < n) { g_deg[i] = 0.f; g_cnt[i] = 0; }
    if (i == 0) {
        const long long* q = (const long long*)ei;
        int ok64 = 1;
        int lim = (2 * E < 64) ? 2 * E : 64;
        for (int j = 0; j < lim; j++) {
            long long v = q[j];
            if (v < 0 || v >= (long long)n) { ok64 = 0; break; }
        }
        g_is64 = ok64;
    }
}

// convert x, w1, w2 to fp16; zero x pad rows. Element-group i covers 4 floats.
__global__ void k_tohalf(const float* __restrict__ x,
                         const float* __restrict__ w1,
                         const float* __restrict__ w2, int N) {
    const int XQ  = NMAX_PAD * IN_C / 4;            // x quads (padded)
    const int W1Q = IN_C * HID_C / 4;
    const int W2Q = HID_C * OUT_C / 4;
    int i = blockIdx.x * blockDim.x + threadIdx.x;
    if (i < XQ) {
        float4 v = (i < N * IN_C / 4) ? *(const float4*)&x[i * 4]
                                      : make_float4(0.f, 0.f, 0.f, 0.f);
        store4e(g_xh, (size_t)i * 4, v);
    } else if (i < XQ + W1Q) {
        int j = i - XQ;
        store4e(g_w1h, (size_t)j * 4, *(const float4*)&w1[j * 4]);
    } else if (i < XQ + W1Q + W2Q) {
        int j = i - XQ - W1Q;
        store4e(g_w2h, (size_t)j * 4, *(const float4*)&w2[j * 4]);
    }
}

__global__ void k_deg(const void* __restrict__ ei,
                      const float* __restrict__ ea, int E, int N) {
    int e = blockIdx.x * blockDim.x + threadIdx.x;
    if (e < E) {
        int is64 = g_is64;
        int r = load_idx(ei, e, is64);
        if ((unsigned)r < (unsigned)N) {
            atomicAdd(&g_deg[r], ea[e]);
            atomicAdd(&g_cnt[r], 1);
        }
    }
}

// ---- parallel exclusive scan of g_cnt -> g_rowptr / g_cur ----
__global__ __launch_bounds__(256) void k_bsum(int n) {
    __shared__ int sh[256];
    int tid = threadIdx.x;
    int i = blockIdx.x * 256 + tid;
    sh[tid] = (i < n) ? g_cnt[i] : 0;
    __syncthreads();
    for (int off = 128; off > 0; off >>= 1) {
        if (tid < off) sh[tid] += sh[tid + off];
        __syncthreads();
    }
    if (tid == 0) g_bsum[blockIdx.x] = sh[0];
}

__global__ __launch_bounds__(256) void k_bscan(int nb) {
    __shared__ int sh[256];
    int tid = threadIdx.x;
    int v = (tid < nb) ? g_bsum[tid] : 0;
    sh[tid] = v;
    __syncthreads();
    for (int off = 1; off < 256; off <<= 1) {
        int t = (tid >= off) ? sh[tid - off] : 0;
        __syncthreads();
        sh[tid] += t;
        __syncthreads();
    }
    if (tid < nb) g_bsum[tid] = sh[tid] - v;
}

__global__ __launch_bounds__(256) void k_rowptr(int n) {
    __shared__ int sh[256];
    int tid = threadIdx.x;
    int i = blockIdx.x * 256 + tid;
    int v = (i < n) ? g_cnt[i] : 0;
    sh[tid] = v;
    __syncthreads();
    for (int off = 1; off < 256; off <<= 1) {
        int t = (tid >= off) ? sh[tid - off] : 0;
        __syncthreads();
        sh[tid] += t;
        __syncthreads();
    }
    int incl = sh[tid];
    int base = g_bsum[blockIdx.x];
    if (i < n) {
        int ex = base + incl - v;
        g_rowptr[i] = ex;
        g_cur[i]    = ex;
        if (i == n - 1) g_rowptr[n] = base + incl;
    }
}

__global__ void k_scatter(const void* __restrict__ ei,
                          const float* __restrict__ ea, int E, int N) {
    int e = blockIdx.x * blockDim.x + threadIdx.x;
    if (e < E) {
        int is64 = g_is64;
        int r = load_idx(ei, e, is64);
        int c = load_idx(ei, (size_t)E + e, is64);
        if ((unsigned)r < (unsigned)N && (unsigned)c < (unsigned)N) {
            int pos = atomicAdd(&g_cur[r], 1);
            float v = ea[e] / g_deg[r];   // deg >= 0.1 for any row with an edge
            g_cv[pos] = make_int2(c, __float_as_int(v));
        }
    }
}

// ---------------- tensor-core GEMM: out = A[NP,128] @ B[128,CT] (fp16, fp32 acc)
// warp computes 32 rows x 64 cols as 2x4 wmma 16x16x16 frags; K=128 in 8 steps.
// A/B frags loaded straight from global (L1-resident reuse); epilogue staged
// in smem (32x68 fp32 per warp) then written as coalesced fp16.
#define STG_LD 68
#define MMA_SMEM (8 * 32 * STG_LD * (int)sizeof(float))

template <int CT>
__global__ __launch_bounds__(256) void k_gemm_mma(const __half* __restrict__ A,
                                                  const __half* __restrict__ B,
                                                  __half* __restrict__ out,
                                                  int ntiles) {
    extern __shared__ float stage_sm[];
    int wib  = threadIdx.x >> 5;                 // warp in block
    int lane = threadIdx.x & 31;
    int warp = blockIdx.x * 8 + wib;             // global row-tile id
    if (warp >= ntiles) return;
    int rowbase = warp * 32;
    float* stage = stage_sm + wib * 32 * STG_LD;

    wmma::fragment<wmma::matrix_a, 16, 16, 16, __half, wmma::row_major> af[2];
    wmma::fragment<wmma::matrix_b, 16, 16, 16, __half, wmma::row_major> bf;

#pragma unroll
    for (int half_ = 0; half_ < CT / 64; half_++) {
        int colbase = half_ * 64;
        wmma::fragment<wmma::accumulator, 16, 16, 16, float> acc[2][4];
#pragma unroll
        for (int m = 0; m < 2; m++)
#pragma unroll
            for (int nn = 0; nn < 4; nn++)
                wmma::fill_fragment(acc[m][nn], 0.f);

#pragma unroll
        for (int k = 0; k < 128; k += 16) {
            wmma::load_matrix_sync(af[0], A + (size_t)rowbase * 128 + k, 128);
            wmma::load_matrix_sync(af[1], A + (size_t)(rowbase + 16) * 128 + k, 128);
#pragma unroll
            for (int nn = 0; nn < 4; nn++) {
                wmma::load_matrix_sync(bf, B + (size_t)k * CT + colbase + nn * 16, CT);
                wmma::mma_sync(acc[0][nn], af[0], bf, acc[0][nn]);
                wmma::mma_sync(acc[1][nn], af[1], bf, acc[1][nn]);
            }
        }

        // stage fp32 -> smem, then coalesced fp16 writes
#pragma unroll
        for (int m = 0; m < 2; m++)
#pragma unroll
            for (int nn = 0; nn < 4; nn++)
                wmma::store_matrix_sync(stage + m * 16 * STG_LD + nn * 16,
                                        acc[m][nn], STG_LD, wmma::mem_row_major);
        __syncwarp();
        // each lane writes one row (32 rows, 64 cols)
        {
            const float* srow = stage + lane * STG_LD;
            size_t gbase = (size_t)(rowbase + lane) * CT + colbase;
#pragma unroll
            for (int c = 0; c < 64; c += 4) {
                float4 v = *(const float4*)&srow[c];
                store4e(out, gbase + c, v);
            }
        }
        __syncwarp();
    }
}

// ---------------- SPMM ----------------
// EPI: 0 = none, 1 = relu(+bias), 2 = sigmoid(+bias), 3 = sigmoid (no bias)
template <int F, int EPI, typename SrcT, typename DstT>
__global__ __launch_bounds__(256) void k_spmm(const SrcT* __restrict__ src,
                                              const float* __restrict__ bias,
                                              DstT* __restrict__ dst, int n) {
    int w = (blockIdx.x * blockDim.x + threadIdx.x) >> 5;
    int lane = threadIdx.x & 31;
    if (w >= n) return;
    int beg = g_rowptr[w];
    int end = g_rowptr[w + 1];

    if constexpr (F == 128) {
        float4 acc = {0.f, 0.f, 0.f, 0.f};
        int j = beg;
        for (; j + 3 < end; j += 4) {
            int2 cv0 = g_cv[j];
            int2 cv1 = g_cv[j + 1];
            int2 cv2 = g_cv[j + 2];
            int2 cv3 = g_cv[j + 3];
            float4 s0 = gather4(src, cv0.x, lane);
            float4 s1 = gather4(src, cv1.x, lane);
            float4 s2 = gather4(src, cv2.x, lane);
            float4 s3 = gather4(src, cv3.x, lane);
            float v0 = __int_as_float(cv0.y);
            float v1 = __int_as_float(cv1.y);
            float v2 = __int_as_float(cv2.y);
            float v3 = __int_as_float(cv3.y);
            acc.x += v0 * s0.x; acc.y += v0 * s0.y; acc.z += v0 * s0.z; acc.w += v0 * s0.w;
            acc.x += v1 * s1.x; acc.y += v1 * s1.y; acc.z += v1 * s1.z; acc.w += v1 * s1.w;
            acc.x += v2 * s2.x; acc.y += v2 * s2.y; acc.z += v2 * s2.z; acc.w += v2 * s2.w;
            acc.x += v3 * s3.x; acc.y += v3 * s3.y; acc.z += v3 * s3.z; acc.w += v3 * s3.w;
        }
        for (; j < end; j++) {
            int2 cv = g_cv[j];
            float v = __int_as_float(cv.y);
            float4 s = gather4(src, cv.x, lane);
            acc.x += v * s.x; acc.y += v * s.y; acc.z += v * s.z; acc.w += v * s.w;
        }
        if (EPI == 1) {
            float4 b = *(const float4*)&bias[lane * 4];
            acc.x = fmaxf(acc.x + b.x, 0.f);
            acc.y = fmaxf(acc.y + b.y, 0.f);
            acc.z = fmaxf(acc.z + b.z, 0.f);
            acc.w = fmaxf(acc.w + b.w, 0.f);
        }
        store4e(dst, (size_t)w * 128 + lane * 4, acc);
    } else {  // F == 64
        float2 acc = {0.f, 0.f};
        int j = beg;
        for (; j + 3 < end; j += 4) {
            int2 cv0 = g_cv[j];
            int2 cv1 = g_cv[j + 1];
            int2 cv2 = g_cv[j + 2];
            int2 cv3 = g_cv[j + 3];
            float2 s0 = gather2(src, cv0.x, lane);
            float2 s1 = gather2(src, cv1.x, lane);
            float2 s2 = gather2(src, cv2.x, lane);
            float2 s3 = gather2(src, cv3.x, lane);
            float v0 = __int_as_float(cv0.y);
            float v1 = __int_as_float(cv1.y);
            float v2 = __int_as_float(cv2.y);
            float v3 = __int_as_float(cv3.y);
            acc.x += v0 * s0.x; acc.y += v0 * s0.y;
            acc.x += v1 * s1.x; acc.y += v1 * s1.y;
            acc.x += v2 * s2.x; acc.y += v2 * s2.y;
            acc.x += v3 * s3.x; acc.y += v3 * s3.y;
        }
        for (; j < end; j++) {
            int2 cv = g_cv[j];
            float v = __int_as_float(cv.y);
            float2 s = gather2(src, cv.x, lane);
            acc.x += v * s.x; acc.y += v * s.y;
        }
        if (EPI == 2) {
            float2 b = *(const float2*)&bias[lane * 2];
            acc.x = 1.f / (1.f + __expf(-(acc.x + b.x)));
            acc.y = 1.f / (1.f + __expf(-(acc.y + b.y)));
        } else if (EPI == 3) {
            acc.x = 1.f / (1.f + __expf(-acc.x));
            acc.y = 1.f / (1.f + __expf(-acc.y));
        }
        store2e(dst, (size_t)w * 64 + lane * 2, acc);
    }
}

// ---------------- host launch ----------------
static void* sym_addr(const void* sym) {
    void* p = nullptr;
    cudaGetSymbolAddress(&p, sym);
    return p;
}

extern "C" void kernel_launch(void* const* d_in, const int* in_sizes, int n_in,
                              void* d_out, int out_size) {
    const float* x    = (const float*)d_in[0];
    const float* soft = (const float*)d_in[1];
    const float* ea   = (const float*)d_in[2];
    const float* w1   = (const float*)d_in[3];
    const float* b1   = (const float*)d_in[4];
    const float* w2   = (const float*)d_in[5];
    const float* b2   = (const float*)d_in[6];
    const void*  ei   = (const void*)d_in[7];

    int N = in_sizes[0] / IN_C;
    int E = in_sizes[2];

    float* out     = (float*)d_out;
    float* out_x   = out;
    float* out_lab = out + (size_t)N * OUT_C;

    __half* xh  = (__half*)sym_addr(g_xh);
    __half* w1h = (__half*)sym_addr(g_w1h);
    __half* w2h = (__half*)sym_addr(g_w2h);
    __half* xw  = (__half*)sym_addr(g_xw);
    __half* h   = (__half*)sym_addr(g_h);
    __half* hw  = (__half*)sym_addr(g_hw);
    __half* la  = (__half*)sym_addr(g_lab);
    __half* lb  = la + (size_t)NMAX * OUT_C;

    cudaFuncSetAttribute(k_gemm_mma<128>, cudaFuncAttributeMaxDynamicSharedMemorySize, MMA_SMEM);
    cudaFuncSetAttribute(k_gemm_mma<64>,  cudaFuncAttributeMaxDynamicSharedMemorySize, MMA_SMEM);

    int tb = 256;
    int nb = (N + 255) / 256;
    int spmm_blocks = (N + 7) / 8;
    int ntiles = (N + 31) / 32;                 // 1563
    int mma_blocks = (ntiles + 7) / 8;          // 196
    int convq = (NMAX_PAD * IN_C + IN_C * HID_C + HID_C * OUT_C) / 4;

    k_zero  <<<(N + tb - 1) / tb, tb>>>(ei, E, N);                   // 0
    k_tohalf<<<(convq + tb - 1) / tb, tb>>>(x, w1, w2, N);           // 1
    k_deg   <<<(E + tb - 1) / tb, tb>>>(ei, ea, E, N);               // 2

    k_gemm_mma<128><<<mma_blocks, 256, MMA_SMEM>>>(xh, w1h, xw, ntiles); // 3 <- profiled

    k_bsum  <<<nb, 256>>>(N);                                        // 4
    k_bscan <<<1, 256>>>(nb);                                        // 5
    k_rowptr<<<nb, 256>>>(N);                                        // 6
    k_scatter<<<(E + tb - 1) / tb, tb>>>(ei, ea, E, N);              // 7

    k_spmm<128, 1, __half, __half><<<spmm_blocks, 256>>>(xw, b1, h, N);        // 8

    k_spmm<64, 0, float, __half><<<spmm_blocks, 256>>>(soft, nullptr, la, N);  // 9  (LPA 1)

    k_gemm_mma<64><<<mma_blocks, 256, MMA_SMEM>>>(h, w2h, hw, ntiles);         // 10

    k_spmm<64, 0, __half, __half><<<spmm_blocks, 256>>>(la, nullptr, lb, N);   // 11 (LPA 2)
    k_spmm<64, 2, __half, float ><<<spmm_blocks, 256>>>(hw, b2, out_x, N);     // 12
    k_spmm<64, 0, __half, __half><<<spmm_blocks, 256>>>(lb, nullptr, la, N);   // 13 (LPA 3)
    k_spmm<64, 0, __half, __half><<<spmm_blocks, 256>>>(la, nullptr, lb, N);   // 14 (LPA 4)
    k_spmm<64, 3, __half, float ><<<spmm_blocks, 256>>>(lb, nullptr, out_lab, N); // 15 (LPA 5)
}

// round 16
// speedup vs baseline: 1.8970x; 1.2330x over previous
#include <cuda_runtime.h>
#include <cuda_fp16.h>
#include <mma.h>
#include <math.h>

using namespace nvcuda;

// Problem constants (fixed by the dataset)
#define NMAX     50000
#define NMAX_PAD 50048      // multiple of 128 (block row-tile)
#define EMAX     800000
#define IN_C     128
#define HID_C    128
#define OUT_C    64

// ---------------- device scratch (no allocations allowed) ----------------
__device__ int    g_is64;
__device__ float  g_deg [NMAX];
__device__ int    g_cnt [NMAX];
__device__ int    g_bsum[256];
__device__ int    g_rowptr[NMAX + 1];
__device__ int    g_cur [NMAX];
__device__ int2   g_cv  [EMAX];
__device__ __half g_xh  [NMAX_PAD * IN_C];    // x in fp16 (pad rows zero)
__device__ __half g_w1h [IN_C * HID_C];
__device__ __half g_w2h [HID_C * OUT_C];
__device__ __half g_xw  [NMAX_PAD * HID_C];   // x @ w1
__device__ __half g_h   [NMAX_PAD * HID_C];   // relu(spmm(xw)+b1)  (pad rows stay 0)
__device__ __half g_hw  [NMAX_PAD * OUT_C];   // h @ w2
__device__ __half g_lab [2][NMAX * OUT_C];    // LPA ping-pong

__device__ __forceinline__ int load_idx(const void* p, size_t i, int is64) {
    if (is64) return (int)((const long long*)p)[i];
    return ((const int*)p)[i];
}

// ---------------- gather/store helpers ----------------
__device__ __forceinline__ float4 gather4(const __half* src, int col, int lane) {
    uint2 raw = *(const uint2*)&src[(size_t)col * 128 + lane * 4];
    float2 lo = __half22float2(*(__half2*)&raw.x);
    float2 hi = __half22float2(*(__half2*)&raw.y);
    return make_float4(lo.x, lo.y, hi.x, hi.y);
}
__device__ __forceinline__ float2 gather2(const float* src, int col, int lane) {
    return *(const float2*)&src[(size_t)col * 64 + lane * 2];
}
__device__ __forceinline__ float2 gather2(const __half* src, int col, int lane) {
    return __half22float2(*(const __half2*)&src[(size_t)col * 64 + lane * 2]);
}
__device__ __forceinline__ void store4e(float* dst, size_t idx, float4 v) {
    *(float4*)&dst[idx] = v;
}
__device__ __forceinline__ void store4e(__half* dst, size_t idx, float4 v) {
    __half2 h0 = __floats2half2_rn(v.x, v.y);
    __half2 h1 = __floats2half2_rn(v.z, v.w);
    uint2 raw = {*(unsigned*)&h0, *(unsigned*)&h1};
    *(uint2*)&dst[idx] = raw;
}
__device__ __forceinline__ void store2e(float* dst, size_t idx, float2 v) {
    *(float2*)&dst[idx] = v;
}
__device__ __forceinline__ void store2e(__half* dst, size_t idx, float2 v) {
    *(__half2*)&dst[idx] = __floats2half2_rn(v.x, v.y);
}

// ---------------- preprocessing kernels ----------------
__global__ void k_zero(const void* __restrict__ ei, int E, int n) {
    int i = blockIdx.x * blockDim.x + threadIdx.x;
    if (i < n) { g_deg[i] = 0.f; g_cnt[i] = 0; }
    if (i == 0) {
        const long long* q = (const long long*)ei;
        int ok64 = 1;
        int lim = (2 * E < 64) ? 2 * E : 64;
        for (int j = 0; j < lim; j++) {
            long long v = q[j];
            if (v < 0 || v >= (long long)n) { ok64 = 0; break; }
        }
        g_is64 = ok64;
    }
}

// convert x, w1, w2 to fp16; zero x pad rows. Element-group i covers 4 floats.
__global__ void k_tohalf(const float* __restrict__ x,
                         const float* __restrict__ w1,
                         const float* __restrict__ w2, int N) {
    const int XQ  = NMAX_PAD * IN_C / 4;            // x quads (padded)
    const int W1Q = IN_C * HID_C / 4;
    const int W2Q = HID_C * OUT_C / 4;
    int i = blockIdx.x * blockDim.x + threadIdx.x;
    if (i < XQ) {
        float4 v = (i < N * IN_C / 4) ? *(const float4*)&x[i * 4]
                                      : make_float4(0.f, 0.f, 0.f, 0.f);
        store4e(g_xh, (size_t)i * 4, v);
    } else if (i < XQ + W1Q) {
        int j = i - XQ;
        store4e(g_w1h, (size_t)j * 4, *(const float4*)&w1[j * 4]);
    } else if (i < XQ + W1Q + W2Q) {
        int j = i - XQ - W1Q;
        store4e(g_w2h, (size_t)j * 4, *(const float4*)&w2[j * 4]);
    }
}

__global__ void k_deg(const void* __restrict__ ei,
                      const float* __restrict__ ea, int E, int N) {
    int e = blockIdx.x * blockDim.x + threadIdx.x;
    if (e < E) {
        int is64 = g_is64;
        int r = load_idx(ei, e, is64);
        if ((unsigned)r < (unsigned)N) {
            atomicAdd(&g_deg[r], ea[e]);
            atomicAdd(&g_cnt[r], 1);
        }
    }
}

// ---- parallel exclusive scan of g_cnt -> g_rowptr / g_cur ----
__global__ __launch_bounds__(256) void k_bsum(int n) {
    __shared__ int sh[256];
    int tid = threadIdx.x;
    int i = blockIdx.x * 256 + tid;
    sh[tid] = (i < n) ? g_cnt[i] : 0;
    __syncthreads();
    for (int off = 128; off > 0; off >>= 1) {
        if (tid < off) sh[tid] += sh[tid + off];
        __syncthreads();
    }
    if (tid == 0) g_bsum[blockIdx.x] = sh[0];
}

__global__ __launch_bounds__(256) void k_bscan(int nb) {
    __shared__ int sh[256];
    int tid = threadIdx.x;
    int v = (tid < nb) ? g_bsum[tid] : 0;
    sh[tid] = v;
    __syncthreads();
    for (int off = 1; off < 256; off <<= 1) {
        int t = (tid >= off) ? sh[tid - off] : 0;
        __syncthreads();
        sh[tid] += t;
        __syncthreads();
    }
    if (tid < nb) g_bsum[tid] = sh[tid] - v;
}

__global__ __launch_bounds__(256) void k_rowptr(int n) {
    __shared__ int sh[256];
    int tid = threadIdx.x;
    int i = blockIdx.x * 256 + tid;
    int v = (i < n) ? g_cnt[i] : 0;
    sh[tid] = v;
    __syncthreads();
    for (int off = 1; off < 256; off <<= 1) {
        int t = (tid >= off) ? sh[tid - off] : 0;
        __syncthreads();
        sh[tid] += t;
        __syncthreads();
    }
    int incl = sh[tid];
    int base = g_bsum[blockIdx.x];
    if (i < n) {
        int ex = base + incl - v;
        g_rowptr[i] = ex;
        g_cur[i]    = ex;
        if (i == n - 1) g_rowptr[n] = base + incl;
    }
}

__global__ void k_scatter(const void* __restrict__ ei,
                          const float* __restrict__ ea, int E, int N) {
    int e = blockIdx.x * blockDim.x + threadIdx.x;
    if (e < E) {
        int is64 = g_is64;
        int r = load_idx(ei, e, is64);
        int c = load_idx(ei, (size_t)E + e, is64);
        if ((unsigned)r < (unsigned)N && (unsigned)c < (unsigned)N) {
            int pos = atomicAdd(&g_cur[r], 1);
            float v = ea[e] / g_deg[r];   // deg >= 0.1 for any row with an edge
            g_cv[pos] = make_int2(c, __float_as_int(v));
        }
    }
}

// ---------------- tensor-core GEMM: out = A[NP,128] @ B[128,CT] (fp16, fp32 acc)
// Block: 256 thr / 8 warps, tile 128 rows x 64 cols. Whole K=128 staged in smem
// once (no k-loop staging needed), then 8 wmma k-steps from smem.
// Warp grid 4x2: each warp owns 32x32 (2x2 frags). Epilogue converts accum
// frags to fp16 in registers and stores direct to global.
#define A_LD 136
#define B_LD 72
#define MMA_SMEM ((128 * A_LD + 128 * B_LD) * (int)sizeof(__half))

template <int CT>
__global__ __launch_bounds__(256) void k_gemm_mma(const __half* __restrict__ A,
                                                  const __half* __restrict__ B,
                                                  __half* __restrict__ out) {
    extern __shared__ __half sm[];
    __half* As = sm;                    // [128][A_LD]
    __half* Bs = sm + 128 * A_LD;       // [128][B_LD]
    int rowbase = blockIdx.x * 128;
    int colbase = blockIdx.y * 64;
    int tid = threadIdx.x;

    // load A tile: 128x128 halfs = 2048 uint4; 256 thr -> 8 each
#pragma unroll
    for (int i = tid; i < 128 * 16; i += 256) {
        int r = i >> 4, c8 = i & 15;
        *(uint4*)&As[r * A_LD + c8 * 8] =
            *(const uint4*)&A[(size_t)(rowbase + r) * 128 + c8 * 8];
    }
    // load B tile: 128x64 halfs = 1024 uint4 -> 4 each
#pragma unroll
    for (int i = tid; i < 128 * 8; i += 256) {
        int r = i >> 3, c8 = i & 7;
        *(uint4*)&Bs[r * B_LD + c8 * 8] =
            *(const uint4*)&B[(size_t)r * CT + colbase + c8 * 8];
    }
    __syncthreads();

    int wid = tid >> 5;
    int wr = wid >> 1;          // 0..3: 32-row group
    int wc = wid & 1;           // 0..1: 32-col group

    wmma::fragment<wmma::matrix_a, 16, 16, 16, __half, wmma::row_major> af[2];
    wmma::fragment<wmma::matrix_b, 16, 16, 16, __half, wmma::row_major> bf[2];
    wmma::fragment<wmma::accumulator, 16, 16, 16, float> acc[2][2];
#pragma unroll
    for (int m = 0; m < 2; m++)
#pragma unroll
        for (int nn = 0; nn < 2; nn++)
            wmma::fill_fragment(acc[m][nn], 0.f);

#pragma unroll
    for (int k = 0; k < 128; k += 16) {
        wmma::load_matrix_sync(af[0], As + (wr * 32) * A_LD + k, A_LD);
        wmma::load_matrix_sync(af[1], As + (wr * 32 + 16) * A_LD + k, A_LD);
        wmma::load_matrix_sync(bf[0], Bs + k * B_LD + wc * 32, B_LD);
        wmma::load_matrix_sync(bf[1], Bs + k * B_LD + wc * 32 + 16, B_LD);
#pragma unroll
        for (int m = 0; m < 2; m++)
#pragma unroll
            for (int nn = 0; nn < 2; nn++)
                wmma::mma_sync(acc[m][nn], af[m], bf[nn], acc[m][nn]);
    }

    // epilogue: fp32 accum -> fp16 frag in registers, store direct to global
    wmma::fragment<wmma::accumulator, 16, 16, 16, __half> hf;
#pragma unroll
    for (int m = 0; m < 2; m++)
#pragma unroll
        for (int nn = 0; nn < 2; nn++) {
#pragma unroll
            for (int e = 0; e < hf.num_elements; e++)
                hf.x[e] = __float2half(acc[m][nn].x[e]);
            wmma::store_matrix_sync(
                out + (size_t)(rowbase + wr * 32 + m * 16) * CT + colbase + wc * 32 + nn * 16,
                hf, CT, wmma::mem_row_major);
        }
}

// ---------------- SPMM ----------------
// EPI: 0 = none, 1 = relu(+bias), 2 = sigmoid(+bias), 3 = sigmoid (no bias)
template <int F, int EPI, typename SrcT, typename DstT>
__global__ __launch_bounds__(256) void k_spmm(const SrcT* __restrict__ src,
                                              const float* __restrict__ bias,
                                              DstT* __restrict__ dst, int n) {
    int w = (blockIdx.x * blockDim.x + threadIdx.x) >> 5;
    int lane = threadIdx.x & 31;
    if (w >= n) return;
    int beg = g_rowptr[w];
    int end = g_rowptr[w + 1];

    if constexpr (F == 128) {
        float4 acc = {0.f, 0.f, 0.f, 0.f};
        int j = beg;
        for (; j + 3 < end; j += 4) {
            int2 cv0 = g_cv[j];
            int2 cv1 = g_cv[j + 1];
            int2 cv2 = g_cv[j + 2];
            int2 cv3 = g_cv[j + 3];
            float4 s0 = gather4(src, cv0.x, lane);
            float4 s1 = gather4(src, cv1.x, lane);
            float4 s2 = gather4(src, cv2.x, lane);
            float4 s3 = gather4(src, cv3.x, lane);
            float v0 = __int_as_float(cv0.y);
            float v1 = __int_as_float(cv1.y);
            float v2 = __int_as_float(cv2.y);
            float v3 = __int_as_float(cv3.y);
            acc.x += v0 * s0.x; acc.y += v0 * s0.y; acc.z += v0 * s0.z; acc.w += v0 * s0.w;
            acc.x += v1 * s1.x; acc.y += v1 * s1.y; acc.z += v1 * s1.z; acc.w += v1 * s1.w;
            acc.x += v2 * s2.x; acc.y += v2 * s2.y; acc.z += v2 * s2.z; acc.w += v2 * s2.w;
            acc.x += v3 * s3.x; acc.y += v3 * s3.y; acc.z += v3 * s3.z; acc.w += v3 * s3.w;
        }
        for (; j < end; j++) {
            int2 cv = g_cv[j];
            float v = __int_as_float(cv.y);
            float4 s = gather4(src, cv.x, lane);
            acc.x += v * s.x; acc.y += v * s.y; acc.z += v * s.z; acc.w += v * s.w;
        }
        if (EPI == 1) {
            float4 b = *(const float4*)&bias[lane * 4];
            acc.x = fmaxf(acc.x + b.x, 0.f);
            acc.y = fmaxf(acc.y + b.y, 0.f);
            acc.z = fmaxf(acc.z + b.z, 0.f);
            acc.w = fmaxf(acc.w + b.w, 0.f);
        }
        store4e(dst, (size_t)w * 128 + lane * 4, acc);
    } else {  // F == 64
        float2 acc = {0.f, 0.f};
        int j = beg;
        for (; j + 3 < end; j += 4) {
            int2 cv0 = g_cv[j];
            int2 cv1 = g_cv[j + 1];
            int2 cv2 = g_cv[j + 2];
            int2 cv3 = g_cv[j + 3];
            float2 s0 = gather2(src, cv0.x, lane);
            float2 s1 = gather2(src, cv1.x, lane);
            float2 s2 = gather2(src, cv2.x, lane);
            float2 s3 = gather2(src, cv3.x, lane);
            float v0 = __int_as_float(cv0.y);
            float v1 = __int_as_float(cv1.y);
            float v2 = __int_as_float(cv2.y);
            float v3 = __int_as_float(cv3.y);
            acc.x += v0 * s0.x; acc.y += v0 * s0.y;
            acc.x += v1 * s1.x; acc.y += v1 * s1.y;
            acc.x += v2 * s2.x; acc.y += v2 * s2.y;
            acc.x += v3 * s3.x; acc.y += v3 * s3.y;
        }
        for (; j < end; j++) {
            int2 cv = g_cv[j];
            float v = __int_as_float(cv.y);
            float2 s = gather2(src, cv.x, lane);
            acc.x += v * s.x; acc.y += v * s.y;
        }
        if (EPI == 2) {
            float2 b = *(const float2*)&bias[lane * 2];
            acc.x = 1.f / (1.f + __expf(-(acc.x + b.x)));
            acc.y = 1.f / (1.f + __expf(-(acc.y + b.y)));
        } else if (EPI == 3) {
            acc.x = 1.f / (1.f + __expf(-acc.x));
            acc.y = 1.f / (1.f + __expf(-acc.y));
        }
        store2e(dst, (size_t)w * 64 + lane * 2, acc);
    }
}

// ---------------- host launch ----------------
static void* sym_addr(const void* sym) {
    void* p = nullptr;
    cudaGetSymbolAddress(&p, sym);
    return p;
}

extern "C" void kernel_launch(void* const* d_in, const int* in_sizes, int n_in,
                              void* d_out, int out_size) {
    const float* x    = (const float*)d_in[0];
    const float* soft = (const float*)d_in[1];
    const float* ea   = (const float*)d_in[2];
    const float* w1   = (const float*)d_in[3];
    const float* b1   = (const float*)d_in[4];
    const float* w2   = (const float*)d_in[5];
    const float* b2   = (const float*)d_in[6];
    const void*  ei   = (const void*)d_in[7];

    int N = in_sizes[0] / IN_C;
    int E = in_sizes[2];

    float* out     = (float*)d_out;
    float* out_x   = out;
    float* out_lab = out + (size_t)N * OUT_C;

    __half* xh  = (__half*)sym_addr(g_xh);
    __half* w1h = (__half*)sym_addr(g_w1h);
    __half* w2h = (__half*)sym_addr(g_w2h);
    __half* xw  = (__half*)sym_addr(g_xw);
    __half* h   = (__half*)sym_addr(g_h);
    __half* hw  = (__half*)sym_addr(g_hw);
    __half* la  = (__half*)sym_addr(g_lab);
    __half* lb  = la + (size_t)NMAX * OUT_C;

    cudaFuncSetAttribute(k_gemm_mma<128>, cudaFuncAttributeMaxDynamicSharedMemorySize, MMA_SMEM);
    cudaFuncSetAttribute(k_gemm_mma<64>,  cudaFuncAttributeMaxDynamicSharedMemorySize, MMA_SMEM);

    int tb = 256;
    int nb = (N + 255) / 256;
    int spmm_blocks = (N + 7) / 8;
    int rowtiles = (N + 127) / 128;             // 391 (NMAX_PAD covers 391*128)
    int convq = (NMAX_PAD * IN_C + IN_C * HID_C + HID_C * OUT_C) / 4;

    k_zero  <<<(N + tb - 1) / tb, tb>>>(ei, E, N);                   // 0
    k_tohalf<<<(convq + tb - 1) / tb, tb>>>(x, w1, w2, N);           // 1
    k_deg   <<<(E + tb - 1) / tb, tb>>>(ei, ea, E, N);               // 2

    dim3 g1(rowtiles, 2);
    k_gemm_mma<128><<<g1, 256, MMA_SMEM>>>(xh, w1h, xw);             // 3 <- profiled

    k_bsum  <<<nb, 256>>>(N);                                        // 4
    k_bscan <<<1, 256>>>(nb);                                        // 5
    k_rowptr<<<nb, 256>>>(N);                                        // 6
    k_scatter<<<(E + tb - 1) / tb, tb>>>(ei, ea, E, N);              // 7

    k_spmm<128, 1, __half, __half><<<spmm_blocks, 256>>>(xw, b1, h, N);        // 8

    k_spmm<64, 0, float, __half><<<spmm_blocks, 256>>>(soft, nullptr, la, N);  // 9  (LPA 1)

    dim3 g2(rowtiles, 1);
    k_gemm_mma<64><<<g2, 256, MMA_SMEM>>>(h, w2h, hw);               // 10

    k_spmm<64, 0, __half, __half><<<spmm_blocks, 256>>>(la, nullptr, lb, N);   // 11 (LPA 2)
    k_spmm<64, 2, __half, float ><<<spmm_blocks, 256>>>(hw, b2, out_x, N);     // 12
    k_spmm<64, 0, __half, __half><<<spmm_blocks, 256>>>(lb, nullptr, la, N);   // 13 (LPA 3)
    k_spmm<64, 0, __half, __half><<<spmm_blocks, 256>>>(la, nullptr, lb, N);   // 14 (LPA 4)
    k_spmm<64, 3, __half, float ><<<spmm_blocks, 256>>>(lb, nullptr, out_lab, N); // 15 (LPA 5)
}

// round 17
// speedup vs baseline: 1.9743x; 1.0408x over previous
#include <cuda_runtime.h>
#include <cuda_fp16.h>
#include <mma.h>
#include <math.h>

using namespace nvcuda;

// Problem constants (fixed by the dataset)
#define NMAX     50000
#define NMAX_PAD 50048      // multiple of 128 (block row-tile)
#define EMAX     800000
#define IN_C     128
#define HID_C    128
#define OUT_C    64

// ---------------- device scratch (no allocations allowed) ----------------
__device__ int    g_is64;
__device__ float  g_deg [NMAX];
__device__ int    g_cnt [NMAX];
__device__ int    g_bsum[256];
__device__ int    g_rowptr[NMAX + 1];
__device__ int    g_cur [NMAX];
__device__ int2   g_cv  [EMAX];
__device__ __half g_xh  [NMAX_PAD * IN_C];    // x in fp16 (pad rows zero)
__device__ __half g_w1h [IN_C * HID_C];
__device__ __half g_w2h [HID_C * OUT_C];
__device__ __half g_xw  [NMAX_PAD * HID_C];   // x @ w1
__device__ __half g_h   [NMAX_PAD * HID_C];   // relu(spmm(xw)+b1)  (pad rows stay 0)
__device__ __half g_hw  [NMAX_PAD * OUT_C];   // h @ w2
__device__ __half g_lab [2][NMAX * OUT_C];    // LPA ping-pong

__device__ __forceinline__ int load_idx(const void* p, size_t i, int is64) {
    if (is64) return (int)((const long long*)p)[i];
    return ((const int*)p)[i];
}

// ---------------- gather/store helpers ----------------
__device__ __forceinline__ float4 gather4(const __half* src, int col, int lane) {
    uint2 raw = *(const uint2*)&src[(size_t)col * 128 + lane * 4];
    float2 lo = __half22float2(*(__half2*)&raw.x);
    float2 hi = __half22float2(*(__half2*)&raw.y);
    return make_float4(lo.x, lo.y, hi.x, hi.y);
}
__device__ __forceinline__ float2 gather2(const float* src, int col, int lane) {
    return *(const float2*)&src[(size_t)col * 64 + lane * 2];
}
__device__ __forceinline__ float2 gather2(const __half* src, int col, int lane) {
    return __half22float2(*(const __half2*)&src[(size_t)col * 64 + lane * 2]);
}
__device__ __forceinline__ void store4e(float* dst, size_t idx, float4 v) {
    *(float4*)&dst[idx] = v;
}
__device__ __forceinline__ void store4e(__half* dst, size_t idx, float4 v) {
    __half2 h0 = __floats2half2_rn(v.x, v.y);
    __half2 h1 = __floats2half2_rn(v.z, v.w);
    uint2 raw = {*(unsigned*)&h0, *(unsigned*)&h1};
    *(uint2*)&dst[idx] = raw;
}
__device__ __forceinline__ void store2e(float* dst, size_t idx, float2 v) {
    *(float2*)&dst[idx] = v;
}
__device__ __forceinline__ void store2e(__half* dst, size_t idx, float2 v) {
    *(__half2*)&dst[idx] = __floats2half2_rn(v.x, v.y);
}

// ---------------- preprocessing kernels ----------------
__global__ void k_zero(const void* __restrict__ ei, int E, int n) {
    int i = blockIdx.x * blockDim.x + threadIdx.x;
    if (i < n) { g_deg[i] = 0.f; g_cnt[i] = 0; }
    if (i == 0) {
        const long long* q = (const long long*)ei;
        int ok64 = 1;
        int lim = (2 * E < 64) ? 2 * E : 64;
        for (int j = 0; j < lim; j++) {
            long long v = q[j];
            if (v < 0 || v >= (long long)n) { ok64 = 0; break; }
        }
        g_is64 = ok64;
    }
}

// convert x, w1, w2 to fp16; zero x pad rows. Element-group i covers 4 floats.
__global__ void k_tohalf(const float* __restrict__ x,
                         const float* __restrict__ w1,
                         const float* __restrict__ w2, int N) {
    const int XQ  = NMAX_PAD * IN_C / 4;            // x quads (padded)
    const int W1Q = IN_C * HID_C / 4;
    const int W2Q = HID_C * OUT_C / 4;
    int i = blockIdx.x * blockDim.x + threadIdx.x;
    if (i < XQ) {
        float4 v = (i < N * IN_C / 4) ? *(const float4*)&x[i * 4]
                                      : make_float4(0.f, 0.f, 0.f, 0.f);
        store4e(g_xh, (size_t)i * 4, v);
    } else if (i < XQ + W1Q) {
        int j = i - XQ;
        store4e(g_w1h, (size_t)j * 4, *(const float4*)&w1[j * 4]);
    } else if (i < XQ + W1Q + W2Q) {
        int j = i - XQ - W1Q;
        store4e(g_w2h, (size_t)j * 4, *(const float4*)&w2[j * 4]);
    }
}

__global__ void k_deg(const void* __restrict__ ei,
                      const float* __restrict__ ea, int E, int N) {
    int e = blockIdx.x * blockDim.x + threadIdx.x;
    if (e < E) {
        int is64 = g_is64;
        int r = load_idx(ei, e, is64);
        if ((unsigned)r < (unsigned)N) {
            atomicAdd(&g_deg[r], ea[e]);
            atomicAdd(&g_cnt[r], 1);
        }
    }
}

// ---- parallel exclusive scan of g_cnt -> g_rowptr / g_cur ----
__global__ __launch_bounds__(256) void k_bsum(int n) {
    __shared__ int sh[256];
    int tid = threadIdx.x;
    int i = blockIdx.x * 256 + tid;
    sh[tid] = (i < n) ? g_cnt[i] : 0;
    __syncthreads();
    for (int off = 128; off > 0; off >>= 1) {
        if (tid < off) sh[tid] += sh[tid + off];
        __syncthreads();
    }
    if (tid == 0) g_bsum[blockIdx.x] = sh[0];
}

__global__ __launch_bounds__(256) void k_bscan(int nb) {
    __shared__ int sh[256];
    int tid = threadIdx.x;
    int v = (tid < nb) ? g_bsum[tid] : 0;
    sh[tid] = v;
    __syncthreads();
    for (int off = 1; off < 256; off <<= 1) {
        int t = (tid >= off) ? sh[tid - off] : 0;
        __syncthreads();
        sh[tid] += t;
        __syncthreads();
    }
    if (tid < nb) g_bsum[tid] = sh[tid] - v;
}

__global__ __launch_bounds__(256) void k_rowptr(int n) {
    __shared__ int sh[256];
    int tid = threadIdx.x;
    int i = blockIdx.x * 256 + tid;
    int v = (i < n) ? g_cnt[i] : 0;
    sh[tid] = v;
    __syncthreads();
    for (int off = 1; off < 256; off <<= 1) {
        int t = (tid >= off) ? sh[tid - off] : 0;
        __syncthreads();
        sh[tid] += t;
        __syncthreads();
    }
    int incl = sh[tid];
    int base = g_bsum[blockIdx.x];
    if (i < n) {
        int ex = base + incl - v;
        g_rowptr[i] = ex;
        g_cur[i]    = ex;
        if (i == n - 1) g_rowptr[n] = base + incl;
    }
}

__global__ void k_scatter(const void* __restrict__ ei,
                          const float* __restrict__ ea, int E, int N) {
    int e = blockIdx.x * blockDim.x + threadIdx.x;
    if (e < E) {
        int is64 = g_is64;
        int r = load_idx(ei, e, is64);
        int c = load_idx(ei, (size_t)E + e, is64);
        if ((unsigned)r < (unsigned)N && (unsigned)c < (unsigned)N) {
            int pos = atomicAdd(&g_cur[r], 1);
            float v = ea[e] / g_deg[r];   // deg >= 0.1 for any row with an edge
            g_cv[pos] = make_int2(c, __float_as_int(v));
        }
    }
}

// ---------------- tensor-core GEMM: out = A[NP,128] @ B[128,CT] (fp16, fp32 acc)
#define A_LD 136
#define B_LD 72
#define MMA_SMEM ((128 * A_LD + 128 * B_LD) * (int)sizeof(__half))

template <int CT>
__global__ __launch_bounds__(256) void k_gemm_mma(const __half* __restrict__ A,
                                                  const __half* __restrict__ B,
                                                  __half* __restrict__ out) {
    extern __shared__ __half sm[];
    __half* As = sm;                    // [128][A_LD]
    __half* Bs = sm + 128 * A_LD;       // [128][B_LD]
    int rowbase = blockIdx.x * 128;
    int colbase = blockIdx.y * 64;
    int tid = threadIdx.x;

#pragma unroll
    for (int i = tid; i < 128 * 16; i += 256) {
        int r = i >> 4, c8 = i & 15;
        *(uint4*)&As[r * A_LD + c8 * 8] =
            *(const uint4*)&A[(size_t)(rowbase + r) * 128 + c8 * 8];
    }
#pragma unroll
    for (int i = tid; i < 128 * 8; i += 256) {
        int r = i >> 3, c8 = i & 7;
        *(uint4*)&Bs[r * B_LD + c8 * 8] =
            *(const uint4*)&B[(size_t)r * CT + colbase + c8 * 8];
    }
    __syncthreads();

    int wid = tid >> 5;
    int wr = wid >> 1;          // 0..3: 32-row group
    int wc = wid & 1;           // 0..1: 32-col group

    wmma::fragment<wmma::matrix_a, 16, 16, 16, __half, wmma::row_major> af[2];
    wmma::fragment<wmma::matrix_b, 16, 16, 16, __half, wmma::row_major> bf[2];
    wmma::fragment<wmma::accumulator, 16, 16, 16, float> acc[2][2];
#pragma unroll
    for (int m = 0; m < 2; m++)
#pragma unroll
        for (int nn = 0; nn < 2; nn++)
            wmma::fill_fragment(acc[m][nn], 0.f);

#pragma unroll
    for (int k = 0; k < 128; k += 16) {
        wmma::load_matrix_sync(af[0], As + (wr * 32) * A_LD + k, A_LD);
        wmma::load_matrix_sync(af[1], As + (wr * 32 + 16) * A_LD + k, A_LD);
        wmma::load_matrix_sync(bf[0], Bs + k * B_LD + wc * 32, B_LD);
        wmma::load_matrix_sync(bf[1], Bs + k * B_LD + wc * 32 + 16, B_LD);
#pragma unroll
        for (int m = 0; m < 2; m++)
#pragma unroll
            for (int nn = 0; nn < 2; nn++)
                wmma::mma_sync(acc[m][nn], af[m], bf[nn], acc[m][nn]);
    }

    wmma::fragment<wmma::accumulator, 16, 16, 16, __half> hf;
#pragma unroll
    for (int m = 0; m < 2; m++)
#pragma unroll
        for (int nn = 0; nn < 2; nn++) {
#pragma unroll
            for (int e = 0; e < hf.num_elements; e++)
                hf.x[e] = __float2half(acc[m][nn].x[e]);
            wmma::store_matrix_sync(
                out + (size_t)(rowbase + wr * 32 + m * 16) * CT + colbase + wc * 32 + nn * 16,
                hf, CT, wmma::mem_row_major);
        }
}

// ---------------- SPMM: dst[r,:] = sum_{j in row r} val_j * src[col_j,:] --
// Lane-parallel edge loading: each lane holds one edge (ONE coalesced LDG.64
// per 32 edges), shfl-broadcast inside the warp. Invalid lanes carry
// (col=0, val=0.0f) so the iteration count rounds up to a multiple of 4 with
// harmless zero-value gathers — no memory loads in the gather dependency chain.
// EPI: 0 = none, 1 = relu(+bias), 2 = sigmoid(+bias), 3 = sigmoid (no bias)
template <int F, int EPI, typename SrcT, typename DstT>
__global__ __launch_bounds__(256) void k_spmm(const SrcT* __restrict__ src,
                                              const float* __restrict__ bias,
                                              DstT* __restrict__ dst, int n) {
    int w = (blockIdx.x * blockDim.x + threadIdx.x) >> 5;
    int lane = threadIdx.x & 31;
    if (w >= n) return;
    int beg = g_rowptr[w];
    int end = g_rowptr[w + 1];

    if constexpr (F == 128) {
        float4 acc = {0.f, 0.f, 0.f, 0.f};
        for (int base = beg; base < end; base += 32) {
            int idx = base + lane;
            int2 cv = (idx < end) ? g_cv[idx] : make_int2(0, 0);
            int m  = min(32, end - base);
            int mR = (m + 3) & ~3;
            for (int j = 0; j < mR; j += 4) {
                int   c0 = __shfl_sync(0xffffffffu, cv.x, j + 0);
                int   c1 = __shfl_sync(0xffffffffu, cv.x, j + 1);
                int   c2 = __shfl_sync(0xffffffffu, cv.x, j + 2);
                int   c3 = __shfl_sync(0xffffffffu, cv.x, j + 3);
                float v0 = __int_as_float(__shfl_sync(0xffffffffu, cv.y, j + 0));
                float v1 = __int_as_float(__shfl_sync(0xffffffffu, cv.y, j + 1));
                float v2 = __int_as_float(__shfl_sync(0xffffffffu, cv.y, j + 2));
                float v3 = __int_as_float(__shfl_sync(0xffffffffu, cv.y, j + 3));
                float4 s0 = gather4(src, c0, lane);
                float4 s1 = gather4(src, c1, lane);
                float4 s2 = gather4(src, c2, lane);
                float4 s3 = gather4(src, c3, lane);
                acc.x += v0 * s0.x; acc.y += v0 * s0.y; acc.z += v0 * s0.z; acc.w += v0 * s0.w;
                acc.x += v1 * s1.x; acc.y += v1 * s1.y; acc.z += v1 * s1.z; acc.w += v1 * s1.w;
                acc.x += v2 * s2.x; acc.y += v2 * s2.y; acc.z += v2 * s2.z; acc.w += v2 * s2.w;
                acc.x += v3 * s3.x; acc.y += v3 * s3.y; acc.z += v3 * s3.z; acc.w += v3 * s3.w;
            }
        }
        if (EPI == 1) {
            float4 b = *(const float4*)&bias[lane * 4];
            acc.x = fmaxf(acc.x + b.x, 0.f);
            acc.y = fmaxf(acc.y + b.y, 0.f);
            acc.z = fmaxf(acc.z + b.z, 0.f);
            acc.w = fmaxf(acc.w + b.w, 0.f);
        }
        store4e(dst, (size_t)w * 128 + lane * 4, acc);
    } else {  // F == 64
        float2 acc = {0.f, 0.f};
        for (int base = beg; base < end; base += 32) {
            int idx = base + lane;
            int2 cv = (idx < end) ? g_cv[idx] : make_int2(0, 0);
            int m  = min(32, end - base);
            int mR = (m + 3) & ~3;
            for (int j = 0; j < mR; j += 4) {
                int   c0 = __shfl_sync(0xffffffffu, cv.x, j + 0);
                int   c1 = __shfl_sync(0xffffffffu, cv.x, j + 1);
                int   c2 = __shfl_sync(0xffffffffu, cv.x, j + 2);
                int   c3 = __shfl_sync(0xffffffffu, cv.x, j + 3);
                float v0 = __int_as_float(__shfl_sync(0xffffffffu, cv.y, j + 0));
                float v1 = __int_as_float(__shfl_sync(0xffffffffu, cv.y, j + 1));
                float v2 = __int_as_float(__shfl_sync(0xffffffffu, cv.y, j + 2));
                float v3 = __int_as_float(__shfl_sync(0xffffffffu, cv.y, j + 3));
                float2 s0 = gather2(src, c0, lane);
                float2 s1 = gather2(src, c1, lane);
                float2 s2 = gather2(src, c2, lane);
                float2 s3 = gather2(src, c3, lane);
                acc.x += v0 * s0.x; acc.y += v0 * s0.y;
                acc.x += v1 * s1.x; acc.y += v1 * s1.y;
                acc.x += v2 * s2.x; acc.y += v2 * s2.y;
                acc.x += v3 * s3.x; acc.y += v3 * s3.y;
            }
        }
        if (EPI == 2) {
            float2 b = *(const float2*)&bias[lane * 2];
            acc.x = 1.f / (1.f + __expf(-(acc.x + b.x)));
            acc.y = 1.f / (1.f + __expf(-(acc.y + b.y)));
        } else if (EPI == 3) {
            acc.x = 1.f / (1.f + __expf(-acc.x));
            acc.y = 1.f / (1.f + __expf(-acc.y));
        }
        store2e(dst, (size_t)w * 64 + lane * 2, acc);
    }
}

// ---------------- host launch ----------------
static void* sym_addr(const void* sym) {
    void* p = nullptr;
    cudaGetSymbolAddress(&p, sym);
    return p;
}

extern "C" void kernel_launch(void* const* d_in, const int* in_sizes, int n_in,
                              void* d_out, int out_size) {
    const float* x    = (const float*)d_in[0];
    const float* soft = (const float*)d_in[1];
    const float* ea   = (const float*)d_in[2];
    const float* w1   = (const float*)d_in[3];
    const float* b1   = (const float*)d_in[4];
    const float* w2   = (const float*)d_in[5];
    const float* b2   = (const float*)d_in[6];
    const void*  ei   = (const void*)d_in[7];

    int N = in_sizes[0] / IN_C;
    int E = in_sizes[2];

    float* out     = (float*)d_out;
    float* out_x   = out;
    float* out_lab = out + (size_t)N * OUT_C;

    __half* xh  = (__half*)sym_addr(g_xh);
    __half* w1h = (__half*)sym_addr(g_w1h);
    __half* w2h = (__half*)sym_addr(g_w2h);
    __half* xw  = (__half*)sym_addr(g_xw);
    __half* h   = (__half*)sym_addr(g_h);
    __half* hw  = (__half*)sym_addr(g_hw);
    __half* la  = (__half*)sym_addr(g_lab);
    __half* lb  = la + (size_t)NMAX * OUT_C;

    cudaFuncSetAttribute(k_gemm_mma<128>, cudaFuncAttributeMaxDynamicSharedMemorySize, MMA_SMEM);
    cudaFuncSetAttribute(k_gemm_mma<64>,  cudaFuncAttributeMaxDynamicSharedMemorySize, MMA_SMEM);

    int tb = 256;
    int nb = (N + 255) / 256;
    int spmm_blocks = (N + 7) / 8;
    int rowtiles = (N + 127) / 128;             // 391 (NMAX_PAD covers 391*128)
    int convq = (NMAX_PAD * IN_C + IN_C * HID_C + HID_C * OUT_C) / 4;

    k_zero  <<<(N + tb - 1) / tb, tb>>>(ei, E, N);                   // 0
    k_tohalf<<<(convq + tb - 1) / tb, tb>>>(x, w1, w2, N);           // 1
    k_deg   <<<(E + tb - 1) / tb, tb>>>(ei, ea, E, N);               // 2

    dim3 g1(rowtiles, 2);
    k_gemm_mma<128><<<g1, 256, MMA_SMEM>>>(xh, w1h, xw);             // 3 <- profiled

    k_bsum  <<<nb, 256>>>(N);                                        // 4
    k_bscan <<<1, 256>>>(nb);                                        // 5
    k_rowptr<<<nb, 256>>>(N);                                        // 6
    k_scatter<<<(E + tb - 1) / tb, tb>>>(ei, ea, E, N);              // 7

    k_spmm<128, 1, __half, __half><<<spmm_blocks, 256>>>(xw, b1, h, N);        // 8

    k_spmm<64, 0, float, __half><<<spmm_blocks, 256>>>(soft, nullptr, la, N);  // 9  (LPA 1)

    dim3 g2(rowtiles, 1);
    k_gemm_mma<64><<<g2, 256, MMA_SMEM>>>(h, w2h, hw);               // 10

    k_spmm<64, 0, __half, __half><<<spmm_blocks, 256>>>(la, nullptr, lb, N);   // 11 (LPA 2)
    k_spmm<64, 2, __half, float ><<<spmm_blocks, 256>>>(hw, b2, out_x, N);     // 12
    k_spmm<64, 0, __half, __half><<<spmm_blocks, 256>>>(lb, nullptr, la, N);   // 13 (LPA 3)
    k_spmm<64, 0, __half, __half><<<spmm_blocks, 256>>>(la, nullptr, lb, N);   // 14 (LPA 4)
    k_spmm<64, 3, __half, float ><<<spmm_blocks, 256>>>(lb, nullptr, out_lab, N); // 15 (LPA 5)
}